// round 5
// baseline (speedup 1.0000x reference)
#include <cuda_runtime.h>
#include <math.h>

#define BATCH 8
#define CH 128
#define NTOK 4096          // H*W
#define NGRP 32
#define CPG 4              // channels per group
#define EPSV 1e-5f
#define ATT_SCALE 0.08838834764831845f  // 1/sqrt(128)

// flash tiles
#define BR 128
#define BC 64
#define DPAD 132           // 128 + 4 pad (bank-conflict avoidance)
#define PPAD 68            // 64 + 4 pad
#define FL_SMEM_FLOATS (BR*DPAD + 2*BC*DPAD + BR*PPAD)
#define FL_SMEM_BYTES (FL_SMEM_FLOATS * 4)

// scratch (static device globals; no allocation allowed)
__device__ float g_normed[BATCH*CH*NTOK];   // NCHW
__device__ float g_q[BATCH*NTOK*CH];        // token-major [b][n][c]
__device__ float g_k[BATCH*NTOK*CH];
__device__ float g_v[BATCH*NTOK*CH];
__device__ float g_attn[BATCH*NTOK*CH];
__device__ float g_mean[BATCH*NGRP];
__device__ float g_rstd[BATCH*NGRP];

// ---------------------------------------------------------------------------
// K1: GroupNorm statistics. One block per (b,g); group data is a contiguous
// 16384-float span in NCHW (channels of a group are adjacent).
// ---------------------------------------------------------------------------
__global__ void gn_stats(const float* __restrict__ x) {
    const int bg = blockIdx.x;                       // b*32 + g
    const float4* p = (const float4*)(x + (size_t)bg * CPG * NTOK);
    const int n4 = CPG * NTOK / 4;                   // 4096 float4s
    float s = 0.f, s2 = 0.f;
    for (int i = threadIdx.x; i < n4; i += blockDim.x) {
        float4 v = p[i];
        s  += v.x + v.y + v.z + v.w;
        s2 += v.x*v.x + v.y*v.y + v.z*v.z + v.w*v.w;
    }
    __shared__ float ss[256], ss2[256];
    ss[threadIdx.x] = s; ss2[threadIdx.x] = s2;
    __syncthreads();
    for (int st = 128; st > 0; st >>= 1) {
        if (threadIdx.x < st) {
            ss[threadIdx.x]  += ss[threadIdx.x + st];
            ss2[threadIdx.x] += ss2[threadIdx.x + st];
        }
        __syncthreads();
    }
    if (threadIdx.x == 0) {
        const float invn = 1.0f / (CPG * NTOK);
        float mu  = ss[0] * invn;
        float var = ss2[0] * invn - mu * mu;
        g_mean[bg] = mu;
        g_rstd[bg] = rsqrtf(var + EPSV);
    }
}

// ---------------------------------------------------------------------------
// K2: apply GroupNorm (affine) -> g_normed (NCHW), vectorized float4.
// ---------------------------------------------------------------------------
__global__ void gn_apply(const float* __restrict__ x,
                         const float* __restrict__ gw,
                         const float* __restrict__ gb) {
    const int idx = blockIdx.x * blockDim.x + threadIdx.x;   // over 1M float4
    const int c_lin = idx >> 10;          // (b*128 + c): each channel = 1024 f4
    const int c = c_lin & (CH - 1);
    const int bg = c_lin >> 2;            // (b*128+c)/4 == b*32 + c/4
    const float mu = g_mean[bg], rs = g_rstd[bg];
    const float a = rs * gw[c];
    const float bb = gb[c] - mu * a;
    float4 v = ((const float4*)x)[idx];
    v.x = v.x * a + bb;  v.y = v.y * a + bb;
    v.z = v.z * a + bb;  v.w = v.w * a + bb;
    ((float4*)g_normed)[idx] = v;
}

// ---------------------------------------------------------------------------
// K3: QKV projections. C[m,o] = sum_k A[m,k]*W[o,k] + bias[o]
// A read straight from NCHW g_normed (m=(b,n) contiguous per k-row -> coalesced).
// BM=64, BN=64, BK=16, 256 threads, 4x4 microtile. Outputs token-major.
// ---------------------------------------------------------------------------
__global__ void qkv_gemm(const float* __restrict__ Wq, const float* __restrict__ bq,
                         const float* __restrict__ Wk, const float* __restrict__ bk,
                         const float* __restrict__ Wv, const float* __restrict__ bv) {
    const int m0 = blockIdx.x * 64;
    const int sel = blockIdx.y >> 1;
    const int o0 = (blockIdx.y & 1) * 64;
    const float* W    = (sel == 0) ? Wq : (sel == 1 ? Wk : Wv);
    const float* bias = (sel == 0) ? bq : (sel == 1 ? bk : bv);
    float* outp       = (sel == 0) ? g_q : (sel == 1 ? g_k : g_v);

    const int bb = m0 >> 12;              // batch (tile never crosses batch)
    const int n0 = m0 & (NTOK - 1);
    const float* Abase = g_normed + (size_t)bb * CH * NTOK + n0;

    __shared__ float As[16][64];
    __shared__ float Bs[16][68];
    const int tid = threadIdx.x, tx = tid & 15, ty = tid >> 4;
    float acc[4][4];
    #pragma unroll
    for (int i = 0; i < 4; i++)
        #pragma unroll
        for (int j = 0; j < 4; j++) acc[i][j] = 0.f;

    for (int k0 = 0; k0 < CH; k0 += 16) {
        const int am = tid & 63, ak = tid >> 6;
        #pragma unroll
        for (int p = 0; p < 4; p++)
            As[ak + 4*p][am] = Abase[(size_t)(k0 + ak + 4*p) * NTOK + am];
        const int bk2 = tid & 15, bo = tid >> 4;
        #pragma unroll
        for (int p = 0; p < 4; p++)
            Bs[bk2][bo + 16*p] = W[(o0 + bo + 16*p) * CH + k0 + bk2];
        __syncthreads();
        #pragma unroll
        for (int kk = 0; kk < 16; kk++) {
            float4 a4 = *(float4*)&As[kk][ty * 4];
            float4 b4 = *(float4*)&Bs[kk][tx * 4];
            float a[4] = {a4.x, a4.y, a4.z, a4.w};
            float b[4] = {b4.x, b4.y, b4.z, b4.w};
            #pragma unroll
            for (int i = 0; i < 4; i++)
                #pragma unroll
                for (int j = 0; j < 4; j++) acc[i][j] += a[i] * b[j];
        }
        __syncthreads();
    }
    float4 bsv = *(const float4*)&bias[o0 + tx * 4];
    #pragma unroll
    for (int i = 0; i < 4; i++) {
        const int m = m0 + ty * 4 + i;
        float4 r;
        r.x = acc[i][0] + bsv.x;  r.y = acc[i][1] + bsv.y;
        r.z = acc[i][2] + bsv.z;  r.w = acc[i][3] + bsv.w;
        *(float4*)&outp[(size_t)m * CH + o0 + tx * 4] = r;
    }
}

// ---------------------------------------------------------------------------
// K4: fp32 flash attention. One CTA = 128 query rows of one batch.
// 256 threads (16x16): S microtile 8 rows x 4 (strided) cols; O 8x8 (strided).
// Strided column ownership (c = tx + 16*u) -> conflict-free Ks/Vs reads.
// ATT_SCALE is folded into the Q tile at load time: s_acc is then the
// already-scaled score, removing per-element scale FMULs from softmax.
// ---------------------------------------------------------------------------
__global__ void __launch_bounds__(256, 1) flash_kernel() {
    extern __shared__ float sm[];
    float* Qs = sm;
    float* Ks = Qs + BR * DPAD;
    float* Vs = Ks + BC * DPAD;
    float* Ps = Vs + BC * DPAD;

    const int blk = blockIdx.x;                 // 0..255
    const int b  = blk >> 5;                    // batch
    const int q0 = (blk & 31) * BR;
    const int tid = threadIdx.x;
    const int tx = tid & 15, ty = tid >> 4;

    {   // load Q tile (128 x 128), pre-scaled by 1/sqrt(C)
        const float* Qg = g_q + ((size_t)b * NTOK + q0) * CH;
        const int r = tid >> 5, c4 = (tid & 31) * 4;
        #pragma unroll
        for (int p = 0; p < 16; p++) {
            const int row = r + 8 * p;
            float4 v = *(const float4*)&Qg[(size_t)row * CH + c4];
            v.x *= ATT_SCALE; v.y *= ATT_SCALE;
            v.z *= ATT_SCALE; v.w *= ATT_SCALE;
            *(float4*)&Qs[row * DPAD + c4] = v;
        }
    }
    float m_i[8], l_i[8], acc_o[8][8];
    #pragma unroll
    for (int i = 0; i < 8; i++) {
        m_i[i] = -1e30f; l_i[i] = 0.f;
        #pragma unroll
        for (int w = 0; w < 8; w++) acc_o[i][w] = 0.f;
    }
    __syncthreads();

    for (int j0 = 0; j0 < NTOK; j0 += BC) {
        {   // load K,V tiles (64 x 128)
            const float* Kg = g_k + ((size_t)b * NTOK + j0) * CH;
            const float* Vg = g_v + ((size_t)b * NTOK + j0) * CH;
            const int r = tid >> 5, c4 = (tid & 31) * 4;
            #pragma unroll
            for (int p = 0; p < 8; p++) {
                const int row = r + 8 * p;
                *(float4*)&Ks[row * DPAD + c4] = *(const float4*)&Kg[(size_t)row * CH + c4];
                *(float4*)&Vs[row * DPAD + c4] = *(const float4*)&Vg[(size_t)row * CH + c4];
            }
        }
        __syncthreads();

        // S = (Q*scale) @ K^T  (already scaled)
        float s_acc[8][4];
        #pragma unroll
        for (int i = 0; i < 8; i++)
            #pragma unroll
            for (int u = 0; u < 4; u++) s_acc[i][u] = 0.f;

        #pragma unroll 2
        for (int k = 0; k < CH; k += 4) {
            float kreg[4][4];
            #pragma unroll
            for (int u = 0; u < 4; u++) {
                float4 k4 = *(float4*)&Ks[(tx + 16*u) * DPAD + k];
                kreg[u][0] = k4.x; kreg[u][1] = k4.y;
                kreg[u][2] = k4.z; kreg[u][3] = k4.w;
            }
            #pragma unroll
            for (int i = 0; i < 8; i++) {
                float4 q4 = *(float4*)&Qs[(ty*8 + i) * DPAD + k];
                float qr[4] = {q4.x, q4.y, q4.z, q4.w};
                #pragma unroll
                for (int u = 0; u < 4; u++)
                    #pragma unroll
                    for (int t = 0; t < 4; t++)
                        s_acc[i][u] += qr[t] * kreg[u][t];
            }
        }

        // online softmax (row stats consistent across the 16 tx lanes)
        #pragma unroll
        for (int i = 0; i < 8; i++) {
            float mx = s_acc[i][0];
            #pragma unroll
            for (int u = 1; u < 4; u++) mx = fmaxf(mx, s_acc[i][u]);
            #pragma unroll
            for (int off = 1; off < 16; off <<= 1)
                mx = fmaxf(mx, __shfl_xor_sync(0xffffffffu, mx, off));
            const float mnew = fmaxf(m_i[i], mx);
            const float alpha = __expf(m_i[i] - mnew);
            float rs = 0.f;
            #pragma unroll
            for (int u = 0; u < 4; u++) {
                const float pe = __expf(s_acc[i][u] - mnew);
                rs += pe;
                Ps[(ty*8 + i) * PPAD + tx + 16*u] = pe;
            }
            #pragma unroll
            for (int off = 1; off < 16; off <<= 1)
                rs += __shfl_xor_sync(0xffffffffu, rs, off);
            l_i[i] = l_i[i] * alpha + rs;
            m_i[i] = mnew;
            #pragma unroll
            for (int w = 0; w < 8; w++) acc_o[i][w] *= alpha;
        }
        __syncthreads();   // Ps visible

        // O += P @ V
        #pragma unroll
        for (int j = 0; j < BC; j += 4) {
            float preg[8][4];
            #pragma unroll
            for (int i = 0; i < 8; i++) {
                float4 p4 = *(float4*)&Ps[(ty*8 + i) * PPAD + j];
                preg[i][0] = p4.x; preg[i][1] = p4.y;
                preg[i][2] = p4.z; preg[i][3] = p4.w;
            }
            #pragma unroll
            for (int t = 0; t < 4; t++) {
                float vreg[8];
                #pragma unroll
                for (int w = 0; w < 8; w++)
                    vreg[w] = Vs[(j + t) * DPAD + tx + 16*w];
                #pragma unroll
                for (int i = 0; i < 8; i++) {
                    const float pp = preg[i][t];
                    #pragma unroll
                    for (int w = 0; w < 8; w++) acc_o[i][w] += pp * vreg[w];
                }
            }
        }
        __syncthreads();   // before Ks/Vs/Ps are overwritten
    }

    float* Og = g_attn + ((size_t)b * NTOK + q0) * CH;
    #pragma unroll
    for (int i = 0; i < 8; i++) {
        const float inv = 1.0f / l_i[i];
        const int row = ty*8 + i;
        #pragma unroll
        for (int w = 0; w < 8; w++)
            Og[(size_t)row * CH + tx + 16*w] = acc_o[i][w] * inv;
    }
}

// ---------------------------------------------------------------------------
// K5: output projection + bias + residual; writes NCHW d_out directly.
// Microtile transposed vs K3 so stores run along n (contiguous in NCHW).
// ---------------------------------------------------------------------------
__global__ void proj_gemm(const float* __restrict__ W,
                          const float* __restrict__ bias,
                          float* __restrict__ out) {
    const int m0 = blockIdx.x * 64;
    const int o0 = blockIdx.y * 64;
    __shared__ float As[16][68];   // [k][m]
    __shared__ float Ws[16][68];   // [k][o]
    const int tid = threadIdx.x, tx = tid & 15, ty = tid >> 4;
    float acc[4][4];               // [o][m]
    #pragma unroll
    for (int i = 0; i < 4; i++)
        #pragma unroll
        for (int j = 0; j < 4; j++) acc[i][j] = 0.f;

    for (int k0 = 0; k0 < CH; k0 += 16) {
        const int ak = tid & 15, am = tid >> 4;
        #pragma unroll
        for (int p = 0; p < 4; p++)
            As[ak][am + 16*p] = g_attn[(size_t)(m0 + am + 16*p) * CH + k0 + ak];
        #pragma unroll
        for (int p = 0; p < 4; p++)
            Ws[ak][am + 16*p] = W[(o0 + am + 16*p) * CH + k0 + ak];
        __syncthreads();
        #pragma unroll
        for (int kk = 0; kk < 16; kk++) {
            float4 w4 = *(float4*)&Ws[kk][ty * 4];
            float4 a4 = *(float4*)&As[kk][tx * 4];
            float wv[4] = {w4.x, w4.y, w4.z, w4.w};
            float av[4] = {a4.x, a4.y, a4.z, a4.w};
            #pragma unroll
            for (int i = 0; i < 4; i++)
                #pragma unroll
                for (int j = 0; j < 4; j++) acc[i][j] += wv[i] * av[j];
        }
        __syncthreads();
    }
    const int bb = m0 >> 12;
    const int n0 = m0 & (NTOK - 1);
    #pragma unroll
    for (int i = 0; i < 4; i++) {
        const int o = o0 + ty * 4 + i;
        const float bo = bias[o];
        const size_t base = ((size_t)bb * CH + o) * NTOK + n0 + tx * 4;
        float4 nv = *(const float4*)&g_normed[base];
        float4 r;
        r.x = acc[i][0] + bo + nv.x;  r.y = acc[i][1] + bo + nv.y;
        r.z = acc[i][2] + bo + nv.z;  r.w = acc[i][3] + bo + nv.w;
        *(float4*)&out[base] = r;
    }
}

// ---------------------------------------------------------------------------
extern "C" void kernel_launch(void* const* d_in, const int* in_sizes, int n_in,
                              void* d_out, int out_size) {
    const float* x   = (const float*)d_in[0];
    const float* gnw = (const float*)d_in[1];
    const float* gnb = (const float*)d_in[2];
    const float* Wq  = (const float*)d_in[3];
    const float* bq  = (const float*)d_in[4];
    const float* Wk  = (const float*)d_in[5];
    const float* bk  = (const float*)d_in[6];
    const float* Wv  = (const float*)d_in[7];
    const float* bv  = (const float*)d_in[8];
    const float* Wp  = (const float*)d_in[9];
    const float* bp  = (const float*)d_in[10];
    float* out = (float*)d_out;

    cudaFuncSetAttribute(flash_kernel,
                         cudaFuncAttributeMaxDynamicSharedMemorySize,
                         FL_SMEM_BYTES);

    gn_stats<<<BATCH * NGRP, 256>>>(x);
    gn_apply<<<(BATCH * CH * NTOK / 4) / 256, 256>>>(x, gnw, gnb);
    qkv_gemm<<<dim3(BATCH * NTOK / 64, 6), 256>>>(Wq, bq, Wk, bk, Wv, bv);
    flash_kernel<<<BATCH * (NTOK / BR), 256, FL_SMEM_BYTES>>>();
    proj_gemm<<<dim3(BATCH * NTOK / 64, CH / 64), 256>>>(Wp, bp, out);
}

// round 6
// speedup vs baseline: 1.5047x; 1.5047x over previous
#include <cuda_runtime.h>
#include <math.h>

#define BATCH 8
#define CH 128
#define NTOK 4096          // H*W
#define NGRP 32
#define CPG 4
#define EPSV 1e-5f
#define ATT_SCALE 0.08838834764831845f  // 1/sqrt(128)

// scratch (static device globals; no allocation allowed)
__device__ float g_normed[BATCH*CH*NTOK];   // NCHW
__device__ float g_q[BATCH*NTOK*CH];        // token-major [b*N+n][c]
__device__ float g_k[BATCH*NTOK*CH];
__device__ float g_v[BATCH*NTOK*CH];
__device__ float g_attn[BATCH*NTOK*CH];
__device__ float g_mean[BATCH*NGRP];
__device__ float g_rstd[BATCH*NGRP];

// ---------------------------------------------------------------------------
// tf32 helpers
// ---------------------------------------------------------------------------
__device__ __forceinline__ unsigned f2tf(float f) {
    unsigned r;
    asm("cvt.rna.tf32.f32 %0, %1;" : "=r"(r) : "f"(f));
    return r;
}
__device__ __forceinline__ void mma8(float* d, const unsigned* a, unsigned b0, unsigned b1) {
    asm volatile(
        "mma.sync.aligned.m16n8k8.row.col.f32.tf32.tf32.f32 "
        "{%0,%1,%2,%3}, {%4,%5,%6,%7}, {%8,%9}, {%0,%1,%2,%3};"
        : "+f"(d[0]), "+f"(d[1]), "+f"(d[2]), "+f"(d[3])
        : "r"(a[0]), "r"(a[1]), "r"(a[2]), "r"(a[3]), "r"(b0), "r"(b1));
}

// Pair-permuted swizzled smem layout, shared by all tiles:
//   row-major [row][pairs], pair q = kt*4 + t holds logical cols (kt*8+t, kt*8+t+4)
//   swizzle: qs = q ^ ((row&3)<<2); uint index = row*2*NP + 2*qs + slot

// ---------------------------------------------------------------------------
// K1: GroupNorm statistics
// ---------------------------------------------------------------------------
__global__ void gn_stats(const float* __restrict__ x) {
    const int bg = blockIdx.x;
    const float4* p = (const float4*)(x + (size_t)bg * CPG * NTOK);
    const int n4 = CPG * NTOK / 4;
    float s = 0.f, s2 = 0.f;
    for (int i = threadIdx.x; i < n4; i += blockDim.x) {
        float4 v = p[i];
        s  += v.x + v.y + v.z + v.w;
        s2 += v.x*v.x + v.y*v.y + v.z*v.z + v.w*v.w;
    }
    __shared__ float ss[256], ss2[256];
    ss[threadIdx.x] = s; ss2[threadIdx.x] = s2;
    __syncthreads();
    for (int st = 128; st > 0; st >>= 1) {
        if (threadIdx.x < st) {
            ss[threadIdx.x]  += ss[threadIdx.x + st];
            ss2[threadIdx.x] += ss2[threadIdx.x + st];
        }
        __syncthreads();
    }
    if (threadIdx.x == 0) {
        const float invn = 1.0f / (CPG * NTOK);
        float mu  = ss[0] * invn;
        float var = ss2[0] * invn - mu * mu;
        g_mean[bg] = mu;
        g_rstd[bg] = rsqrtf(var + EPSV);
    }
}

// ---------------------------------------------------------------------------
// K2: apply GroupNorm
// ---------------------------------------------------------------------------
__global__ void gn_apply(const float* __restrict__ x,
                         const float* __restrict__ gw,
                         const float* __restrict__ gb) {
    const int idx = blockIdx.x * blockDim.x + threadIdx.x;
    const int c_lin = idx >> 10;
    const int c = c_lin & (CH - 1);
    const int bg = c_lin >> 2;
    const float mu = g_mean[bg], rs = g_rstd[bg];
    const float a = rs * gw[c];
    const float bb = gb[c] - mu * a;
    float4 v = ((const float4*)x)[idx];
    v.x = v.x * a + bb;  v.y = v.y * a + bb;
    v.z = v.z * a + bb;  v.w = v.w * a + bb;
    ((float4*)g_normed)[idx] = v;
}

// ---------------------------------------------------------------------------
// K3: QKV projections via tf32 mma. CTA = 128 token-rows x 128 out, K=128.
// blockIdx.y selects q/k/v. A read from NCHW g_normed (coalesced along tokens).
// ---------------------------------------------------------------------------
__global__ void __launch_bounds__(256) qkv_mma(
        const float* __restrict__ Wq, const float* __restrict__ bq,
        const float* __restrict__ Wk, const float* __restrict__ bk,
        const float* __restrict__ Wv, const float* __restrict__ bv) {
    extern __shared__ unsigned Ws[];                 // [128 out][128] swizzled pairs
    const int tid = threadIdx.x;
    const int w = tid >> 5, l = tid & 31, g = l >> 2, t = l & 3;
    const int sel = blockIdx.y;
    const float* W    = (sel == 0) ? Wq : (sel == 1 ? Wk : Wv);
    const float* bias = (sel == 0) ? bq : (sel == 1 ? bk : bv);
    float* outp       = (sel == 0) ? g_q : (sel == 1 ? g_k : g_v);

    // stage W (pairs along in-dim)
    #pragma unroll
    for (int o = 0; o < 2; o++) {
        const int n = o * 64 + w * 8 + g;
        #pragma unroll
        for (int i = 0; i < 16; i++) {
            unsigned v0 = f2tf(W[n * CH + i * 8 + t]);
            unsigned v1 = f2tf(W[n * CH + i * 8 + t + 4]);
            const int qs = (4 * i + t) ^ ((n & 3) << 2);
            *(uint2*)&Ws[n * CH + 2 * qs] = make_uint2(v0, v1);
        }
    }
    __syncthreads();

    const int m0 = blockIdx.x * 128;                 // global token-row base
    const int bb = m0 >> 12;
    const int tok = (m0 & (NTOK - 1)) + w * 16 + g;  // local token of row1
    const float* A = g_normed + (size_t)bb * CH * NTOK;  // [ch][token]

    unsigned aa[16][4];
    #pragma unroll
    for (int kt = 0; kt < 16; kt++) {
        aa[kt][0] = f2tf(A[(size_t)(kt*8 + t    ) * NTOK + tok    ]);
        aa[kt][1] = f2tf(A[(size_t)(kt*8 + t    ) * NTOK + tok + 8]);
        aa[kt][2] = f2tf(A[(size_t)(kt*8 + t + 4) * NTOK + tok    ]);
        aa[kt][3] = f2tf(A[(size_t)(kt*8 + t + 4) * NTOK + tok + 8]);
    }

    float acc[16][4];
    #pragma unroll
    for (int nt = 0; nt < 16; nt++)
        #pragma unroll
        for (int c = 0; c < 4; c++) acc[nt][c] = 0.f;

    const int sw = (g & 3) << 2;
    #pragma unroll
    for (int kt = 0; kt < 16; kt++) {
        const int qs = (kt * 4 + t) ^ sw;
        #pragma unroll
        for (int nt = 0; nt < 16; nt++) {
            uint2 b = *(uint2*)&Ws[(nt*8 + g) * CH + 2 * qs];
            mma8(acc[nt], aa[kt], b.x, b.y);
        }
    }

    const int gm = m0 + w * 16 + g;                  // global row
    #pragma unroll
    for (int nt = 0; nt < 16; nt++) {
        const int ch = nt * 8 + 2 * t;
        const float b0 = bias[ch], b1 = bias[ch + 1];
        float2 v0 = {acc[nt][0] + b0, acc[nt][1] + b1};
        float2 v1 = {acc[nt][2] + b0, acc[nt][3] + b1};
        *(float2*)&outp[(size_t)gm * CH + ch]       = v0;
        *(float2*)&outp[(size_t)(gm + 8) * CH + ch] = v1;
    }
}

// ---------------------------------------------------------------------------
// K4: tf32 mma flash attention. CTA = 128 query rows; 8 warps x 16 rows.
// Q fragments cached in registers; K/V/P in swizzled smem; warp-local softmax.
// ---------------------------------------------------------------------------
#define FL_SMEM_BYTES ((64*128 + 128*64 + 128*64) * 4)   // Ks + Vs + Ps = 96KB

__global__ void __launch_bounds__(256) flash_mma() {
    extern __shared__ unsigned smu[];
    unsigned* Ks = smu;                       // [64 key][128]  pairs along ch
    unsigned* Vs = smu + 64 * 128;            // [128 ch][64]   pairs along key
    unsigned* Ps = smu + 64 * 128 + 128 * 64; // [128 row][64]  pairs along key

    const int blk = blockIdx.x;
    const int b = blk >> 5;
    const int qbase = (blk & 31) * 128;
    const int tid = threadIdx.x;
    const int w = tid >> 5, l = tid & 31, g = l >> 2, t = l & 3;
    const int sw = (g & 3) << 2;
    const int r1 = w * 16 + g;                // local query row (and r1+8)

    // Q fragments (scale folded), 64 regs
    const float* Qg = g_q + ((size_t)(b * NTOK + qbase)) * CH;
    unsigned qa[16][4];
    #pragma unroll
    for (int kt = 0; kt < 16; kt++) {
        qa[kt][0] = f2tf(Qg[(size_t)r1       * CH + kt*8 + t    ] * ATT_SCALE);
        qa[kt][1] = f2tf(Qg[(size_t)(r1 + 8) * CH + kt*8 + t    ] * ATT_SCALE);
        qa[kt][2] = f2tf(Qg[(size_t)r1       * CH + kt*8 + t + 4] * ATT_SCALE);
        qa[kt][3] = f2tf(Qg[(size_t)(r1 + 8) * CH + kt*8 + t + 4] * ATT_SCALE);
    }

    float oacc[16][4];
    #pragma unroll
    for (int nt = 0; nt < 16; nt++)
        #pragma unroll
        for (int c = 0; c < 4; c++) oacc[nt][c] = 0.f;
    float m1 = -1e30f, m2 = -1e30f, l1 = 0.f, l2 = 0.f;

    const float* KgB = g_k + (size_t)b * NTOK * CH;
    const float* VgB = g_v + (size_t)b * NTOK * CH;

    #pragma unroll 1
    for (int j0 = 0; j0 < NTOK; j0 += 64) {
        const float* Kg = KgB + (size_t)j0 * CH;
        const float* Vg = VgB + (size_t)j0 * CH;
        __syncthreads();                       // prior PV reads done
        {   // stage K: [key][ch-pairs]
            const int n = w * 8 + g;           // key 0..63
            #pragma unroll
            for (int i = 0; i < 16; i++) {
                unsigned v0 = f2tf(Kg[n * CH + i*8 + t]);
                unsigned v1 = f2tf(Kg[n * CH + i*8 + t + 4]);
                const int qs = (4*i + t) ^ ((n & 3) << 2);
                *(uint2*)&Ks[n * CH + 2 * qs] = make_uint2(v0, v1);
            }
        }
        #pragma unroll
        for (int o = 0; o < 2; o++) {          // stage V transposed: [ch][key-pairs]
            const int n = o * 64 + w * 8 + g;  // ch 0..127
            #pragma unroll
            for (int i = 0; i < 8; i++) {
                unsigned v0 = f2tf(Vg[(i*8 + t    ) * CH + n]);
                unsigned v1 = f2tf(Vg[(i*8 + t + 4) * CH + n]);
                const int qs = (4*i + t) ^ ((n & 3) << 2);
                *(uint2*)&Vs[n * 64 + 2 * qs] = make_uint2(v0, v1);
            }
        }
        __syncthreads();

        // S = (Q*scale) @ K^T : 8 n-tiles of 8 keys
        float sacc[8][4];
        #pragma unroll
        for (int nt = 0; nt < 8; nt++)
            #pragma unroll
            for (int c = 0; c < 4; c++) sacc[nt][c] = 0.f;
        #pragma unroll
        for (int kt = 0; kt < 16; kt++) {
            const int qs = (kt * 4 + t) ^ sw;
            #pragma unroll
            for (int nt = 0; nt < 8; nt++) {
                uint2 bb2 = *(uint2*)&Ks[(nt*8 + g) * CH + 2 * qs];
                mma8(sacc[nt], qa[kt], bb2.x, bb2.y);
            }
        }

        // online softmax: rows r1 (c0,c1) and r1+8 (c2,c3); quad holds 64 cols
        float mx1 = -1e30f, mx2 = -1e30f;
        #pragma unroll
        for (int nt = 0; nt < 8; nt++) {
            mx1 = fmaxf(mx1, fmaxf(sacc[nt][0], sacc[nt][1]));
            mx2 = fmaxf(mx2, fmaxf(sacc[nt][2], sacc[nt][3]));
        }
        #pragma unroll
        for (int off = 1; off < 4; off <<= 1) {
            mx1 = fmaxf(mx1, __shfl_xor_sync(0xffffffffu, mx1, off));
            mx2 = fmaxf(mx2, __shfl_xor_sync(0xffffffffu, mx2, off));
        }
        const float mn1 = fmaxf(m1, mx1), mn2 = fmaxf(m2, mx2);
        const float al1 = __expf(m1 - mn1), al2 = __expf(m2 - mn2);
        float rs1 = 0.f, rs2 = 0.f;
        const int jj0 = 2 * t, jj1 = 2 * t + 1;
        const int off0 = 2 * ((jj0 & 3) ^ sw) + (jj0 >> 2);   // + nt*8 after ^: careful below
        const int off1 = 2 * ((jj1 & 3) ^ sw) + (jj1 >> 2);
        #pragma unroll
        for (int nt = 0; nt < 8; nt++) {
            float p0 = __expf(sacc[nt][0] - mn1);
            float p1 = __expf(sacc[nt][1] - mn1);
            float p2 = __expf(sacc[nt][2] - mn2);
            float p3 = __expf(sacc[nt][3] - mn2);
            rs1 += p0 + p1;  rs2 += p2 + p3;
            const int i0 = 2 * ((nt*4 + (jj0 & 3)) ^ sw) + (jj0 >> 2);
            const int i1 = 2 * ((nt*4 + (jj1 & 3)) ^ sw) + (jj1 >> 2);
            Ps[r1 * 64 + i0]       = f2tf(p0);
            Ps[r1 * 64 + i1]       = f2tf(p1);
            Ps[(r1 + 8) * 64 + i0] = f2tf(p2);
            Ps[(r1 + 8) * 64 + i1] = f2tf(p3);
        }
        (void)off0; (void)off1;
        #pragma unroll
        for (int off = 1; off < 4; off <<= 1) {
            rs1 += __shfl_xor_sync(0xffffffffu, rs1, off);
            rs2 += __shfl_xor_sync(0xffffffffu, rs2, off);
        }
        l1 = l1 * al1 + rs1;  l2 = l2 * al2 + rs2;
        m1 = mn1;  m2 = mn2;
        #pragma unroll
        for (int nt = 0; nt < 16; nt++) {
            oacc[nt][0] *= al1;  oacc[nt][1] *= al1;
            oacc[nt][2] *= al2;  oacc[nt][3] *= al2;
        }
        __syncwarp();                          // P visible within warp

        // O += P @ V : 16 n-tiles of 8 channels
        #pragma unroll
        for (int kt = 0; kt < 8; kt++) {
            const int qs = (kt * 4 + t) ^ sw;
            uint2 a02 = *(uint2*)&Ps[r1 * 64 + 2 * qs];
            uint2 a13 = *(uint2*)&Ps[(r1 + 8) * 64 + 2 * qs];
            unsigned ar[4] = {a02.x, a13.x, a02.y, a13.y};
            #pragma unroll
            for (int nt = 0; nt < 16; nt++) {
                uint2 bb2 = *(uint2*)&Vs[(nt*8 + g) * 64 + 2 * qs];
                mma8(oacc[nt], ar, bb2.x, bb2.y);
            }
        }
    }

    float* Og = g_attn + ((size_t)(b * NTOK + qbase)) * CH;
    const float inv1 = 1.0f / l1, inv2 = 1.0f / l2;
    #pragma unroll
    for (int nt = 0; nt < 16; nt++) {
        const int ch = nt * 8 + 2 * t;
        float2 v0 = {oacc[nt][0] * inv1, oacc[nt][1] * inv1};
        float2 v1 = {oacc[nt][2] * inv2, oacc[nt][3] * inv2};
        *(float2*)&Og[(size_t)r1 * CH + ch]       = v0;
        *(float2*)&Og[(size_t)(r1 + 8) * CH + ch] = v1;
    }
}

// ---------------------------------------------------------------------------
// K5: output projection via tf32 mma + bias + residual -> NCHW d_out
// ---------------------------------------------------------------------------
__global__ void __launch_bounds__(256) proj_mma(const float* __restrict__ W,
                                                const float* __restrict__ bias,
                                                float* __restrict__ out) {
    extern __shared__ unsigned Ws[];
    const int tid = threadIdx.x;
    const int w = tid >> 5, l = tid & 31, g = l >> 2, t = l & 3;

    #pragma unroll
    for (int o = 0; o < 2; o++) {
        const int n = o * 64 + w * 8 + g;
        #pragma unroll
        for (int i = 0; i < 16; i++) {
            unsigned v0 = f2tf(W[n * CH + i*8 + t]);
            unsigned v1 = f2tf(W[n * CH + i*8 + t + 4]);
            const int qs = (4*i + t) ^ ((n & 3) << 2);
            *(uint2*)&Ws[n * CH + 2 * qs] = make_uint2(v0, v1);
        }
    }
    __syncthreads();

    const int m0 = blockIdx.x * 128;
    const int gm = m0 + w * 16 + g;          // global row into g_attn
    unsigned aa[16][4];
    #pragma unroll
    for (int kt = 0; kt < 16; kt++) {
        aa[kt][0] = f2tf(g_attn[(size_t)gm       * CH + kt*8 + t    ]);
        aa[kt][1] = f2tf(g_attn[(size_t)(gm + 8) * CH + kt*8 + t    ]);
        aa[kt][2] = f2tf(g_attn[(size_t)gm       * CH + kt*8 + t + 4]);
        aa[kt][3] = f2tf(g_attn[(size_t)(gm + 8) * CH + kt*8 + t + 4]);
    }

    float acc[16][4];
    #pragma unroll
    for (int nt = 0; nt < 16; nt++)
        #pragma unroll
        for (int c = 0; c < 4; c++) acc[nt][c] = 0.f;

    const int sw = (g & 3) << 2;
    #pragma unroll
    for (int kt = 0; kt < 16; kt++) {
        const int qs = (kt * 4 + t) ^ sw;
        #pragma unroll
        for (int nt = 0; nt < 16; nt++) {
            uint2 b = *(uint2*)&Ws[(nt*8 + g) * CH + 2 * qs];
            mma8(acc[nt], aa[kt], b.x, b.y);
        }
    }

    // epilogue: NCHW out = acc + bias + normed (residual)
    const int bb = m0 >> 12;
    const int tok = (m0 & (NTOK - 1)) + w * 16 + g;
    #pragma unroll
    for (int nt = 0; nt < 16; nt++) {
        #pragma unroll
        for (int c = 0; c < 2; c++) {
            const int ch = nt * 8 + 2 * t + c;
            const float bo = bias[ch];
            const size_t a0 = ((size_t)bb * CH + ch) * NTOK + tok;
            out[a0]     = acc[nt][c]     + bo + g_normed[a0];
            out[a0 + 8] = acc[nt][c + 2] + bo + g_normed[a0 + 8];
        }
    }
}

// ---------------------------------------------------------------------------
extern "C" void kernel_launch(void* const* d_in, const int* in_sizes, int n_in,
                              void* d_out, int out_size) {
    const float* x   = (const float*)d_in[0];
    const float* gnw = (const float*)d_in[1];
    const float* gnb = (const float*)d_in[2];
    const float* Wq  = (const float*)d_in[3];
    const float* bq  = (const float*)d_in[4];
    const float* Wk  = (const float*)d_in[5];
    const float* bk  = (const float*)d_in[6];
    const float* Wv  = (const float*)d_in[7];
    const float* bv  = (const float*)d_in[8];
    const float* Wp  = (const float*)d_in[9];
    const float* bp  = (const float*)d_in[10];
    float* out = (float*)d_out;

    cudaFuncSetAttribute(flash_mma, cudaFuncAttributeMaxDynamicSharedMemorySize, FL_SMEM_BYTES);
    cudaFuncSetAttribute(qkv_mma,  cudaFuncAttributeMaxDynamicSharedMemorySize, 65536);
    cudaFuncSetAttribute(proj_mma, cudaFuncAttributeMaxDynamicSharedMemorySize, 65536);

    gn_stats<<<BATCH * NGRP, 256>>>(x);
    gn_apply<<<(BATCH * CH * NTOK / 4) / 256, 256>>>(x, gnw, gnb);
    qkv_mma<<<dim3(BATCH * NTOK / 128, 3), 256, 65536>>>(Wq, bq, Wk, bk, Wv, bv);
    flash_mma<<<BATCH * (NTOK / 128), 256, FL_SMEM_BYTES>>>();
    proj_mma<<<BATCH * NTOK / 128, 256, 65536>>>(Wp, bp, out);
}

// round 7
// speedup vs baseline: 3.1200x; 2.0735x over previous
#include <cuda_runtime.h>
#include <math.h>
#include <stdint.h>

#define BATCH 8
#define CH 128
#define NTOK 4096          // H*W
#define NGRP 32
#define CPG 4
#define EPSV 1e-5f
#define ATT_SCALE 0.08838834764831845f  // 1/sqrt(128)

// scratch (static device globals; no allocation allowed)
__device__ float g_normed[BATCH*CH*NTOK];   // NCHW
__device__ float g_q[BATCH*NTOK*CH];        // token-major [b*N+n][c]
__device__ float g_k[BATCH*NTOK*CH];
__device__ float g_v[BATCH*NTOK*CH];
__device__ float g_attn[BATCH*NTOK*CH];
__device__ float g_mean[BATCH*NGRP];
__device__ float g_rstd[BATCH*NGRP];

// ---------------------------------------------------------------------------
// tf32 helpers
// ---------------------------------------------------------------------------
__device__ __forceinline__ unsigned f2tf(float f) {
    unsigned r;
    asm("cvt.rna.tf32.f32 %0, %1;" : "=r"(r) : "f"(f));
    return r;
}
__device__ __forceinline__ void mma8(float* d, const unsigned* a, unsigned b0, unsigned b1) {
    asm volatile(
        "mma.sync.aligned.m16n8k8.row.col.f32.tf32.tf32.f32 "
        "{%0,%1,%2,%3}, {%4,%5,%6,%7}, {%8,%9}, {%0,%1,%2,%3};"
        : "+f"(d[0]), "+f"(d[1]), "+f"(d[2]), "+f"(d[3])
        : "r"(a[0]), "r"(a[1]), "r"(a[2]), "r"(a[3]), "r"(b0), "r"(b1));
}

// ---------------------------------------------------------------------------
// K1: GroupNorm statistics
// ---------------------------------------------------------------------------
__global__ void gn_stats(const float* __restrict__ x) {
    const int bg = blockIdx.x;
    const float4* p = (const float4*)(x + (size_t)bg * CPG * NTOK);
    const int n4 = CPG * NTOK / 4;
    float s = 0.f, s2 = 0.f;
    for (int i = threadIdx.x; i < n4; i += blockDim.x) {
        float4 v = p[i];
        s  += v.x + v.y + v.z + v.w;
        s2 += v.x*v.x + v.y*v.y + v.z*v.z + v.w*v.w;
    }
    __shared__ float ss[256], ss2[256];
    ss[threadIdx.x] = s; ss2[threadIdx.x] = s2;
    __syncthreads();
    for (int st = 128; st > 0; st >>= 1) {
        if (threadIdx.x < st) {
            ss[threadIdx.x]  += ss[threadIdx.x + st];
            ss2[threadIdx.x] += ss2[threadIdx.x + st];
        }
        __syncthreads();
    }
    if (threadIdx.x == 0) {
        const float invn = 1.0f / (CPG * NTOK);
        float mu  = ss[0] * invn;
        float var = ss2[0] * invn - mu * mu;
        g_mean[bg] = mu;
        g_rstd[bg] = rsqrtf(var + EPSV);
    }
}

// ---------------------------------------------------------------------------
// K2: apply GroupNorm
// ---------------------------------------------------------------------------
__global__ void gn_apply(const float* __restrict__ x,
                         const float* __restrict__ gw,
                         const float* __restrict__ gb) {
    const int idx = blockIdx.x * blockDim.x + threadIdx.x;
    const int c_lin = idx >> 10;
    const int c = c_lin & (CH - 1);
    const int bg = c_lin >> 2;
    const float mu = g_mean[bg], rs = g_rstd[bg];
    const float a = rs * gw[c];
    const float bb = gb[c] - mu * a;
    float4 v = ((const float4*)x)[idx];
    v.x = v.x * a + bb;  v.y = v.y * a + bb;
    v.z = v.z * a + bb;  v.w = v.w * a + bb;
    ((float4*)g_normed)[idx] = v;
}

// ---------------------------------------------------------------------------
// K3: QKV projections via tf32 mma (unchanged from R6 — passing)
// ---------------------------------------------------------------------------
__global__ void __launch_bounds__(256) qkv_mma(
        const float* __restrict__ Wq, const float* __restrict__ bq,
        const float* __restrict__ Wk, const float* __restrict__ bk,
        const float* __restrict__ Wv, const float* __restrict__ bv) {
    extern __shared__ unsigned Ws[];
    const int tid = threadIdx.x;
    const int w = tid >> 5, l = tid & 31, g = l >> 2, t = l & 3;
    const int sel = blockIdx.y;
    const float* W    = (sel == 0) ? Wq : (sel == 1 ? Wk : Wv);
    const float* bias = (sel == 0) ? bq : (sel == 1 ? bk : bv);
    float* outp       = (sel == 0) ? g_q : (sel == 1 ? g_k : g_v);

    #pragma unroll
    for (int o = 0; o < 2; o++) {
        const int n = o * 64 + w * 8 + g;
        #pragma unroll
        for (int i = 0; i < 16; i++) {
            unsigned v0 = f2tf(W[n * CH + i * 8 + t]);
            unsigned v1 = f2tf(W[n * CH + i * 8 + t + 4]);
            const int qs = (4 * i + t) ^ ((n & 3) << 2);
            *(uint2*)&Ws[n * CH + 2 * qs] = make_uint2(v0, v1);
        }
    }
    __syncthreads();

    const int m0 = blockIdx.x * 128;
    const int bb = m0 >> 12;
    const int tok = (m0 & (NTOK - 1)) + w * 16 + g;
    const float* A = g_normed + (size_t)bb * CH * NTOK;

    unsigned aa[16][4];
    #pragma unroll
    for (int kt = 0; kt < 16; kt++) {
        aa[kt][0] = f2tf(A[(size_t)(kt*8 + t    ) * NTOK + tok    ]);
        aa[kt][1] = f2tf(A[(size_t)(kt*8 + t    ) * NTOK + tok + 8]);
        aa[kt][2] = f2tf(A[(size_t)(kt*8 + t + 4) * NTOK + tok    ]);
        aa[kt][3] = f2tf(A[(size_t)(kt*8 + t + 4) * NTOK + tok + 8]);
    }

    float acc[16][4];
    #pragma unroll
    for (int nt = 0; nt < 16; nt++)
        #pragma unroll
        for (int c = 0; c < 4; c++) acc[nt][c] = 0.f;

    const int sw = (g & 3) << 2;
    #pragma unroll
    for (int kt = 0; kt < 16; kt++) {
        const int qs = (kt * 4 + t) ^ sw;
        #pragma unroll
        for (int nt = 0; nt < 16; nt++) {
            uint2 b = *(uint2*)&Ws[(nt*8 + g) * CH + 2 * qs];
            mma8(acc[nt], aa[kt], b.x, b.y);
        }
    }

    const int gm = m0 + w * 16 + g;
    #pragma unroll
    for (int nt = 0; nt < 16; nt++) {
        const int ch = nt * 8 + 2 * t;
        const float b0 = bias[ch], b1 = bias[ch + 1];
        float2 v0 = {acc[nt][0] + b0, acc[nt][1] + b1};
        float2 v1 = {acc[nt][2] + b0, acc[nt][3] + b1};
        *(float2*)&outp[(size_t)gm * CH + ch]       = v0;
        *(float2*)&outp[(size_t)(gm + 8) * CH + ch] = v1;
    }
}

// ---------------------------------------------------------------------------
// K4: tf32 flash attention, v2.
//  - K/V tiles: natural row-major [row][128ch], XOR-swizzled at 16B grain:
//        phys float = row*128 + (ch ^ (((row ^ (row>>1)) & 3) << 3))
//  - staged via cp.async.cg (raw fp32 bits as tf32 operands), double-buffered
//  - k-dim permutation pi(t)=2t, pi(t+4)=2t+1 on BOTH GEMMs:
//      * S-phase B fragments = contiguous lds.64 from Ks
//      * P stays entirely in registers (S-acc layout == PV A-frag layout)
// ---------------------------------------------------------------------------
#define TILE_FLOATS 8192                       // 64 rows x 128 ch
#define FL_SMEM_BYTES (4 * TILE_FLOATS * 4)    // K0,V0,K1,V1 = 128KB

__device__ __forceinline__ void stage_tile(const float* __restrict__ Kg,
                                           const float* __restrict__ Vg,
                                           uint32_t dK, uint32_t dV, int tid) {
    #pragma unroll
    for (int u = 0; u < 8; u++) {
        const int h = u * 256 + tid;
        const int row = h >> 5, m = h & 31;
        const uint32_t soff = row * 512 +
            ((m ^ (((row ^ (row >> 1)) & 3) << 1)) << 4);
        asm volatile("cp.async.cg.shared.global [%0], [%1], 16;"
                     :: "r"(dK + soff), "l"(Kg + row * CH + m * 4));
        asm volatile("cp.async.cg.shared.global [%0], [%1], 16;"
                     :: "r"(dV + soff), "l"(Vg + row * CH + m * 4));
    }
    asm volatile("cp.async.commit_group;");
}

__global__ void __launch_bounds__(256) flash_mma() {
    extern __shared__ float smf[];
    const uint32_t smem_base = (uint32_t)__cvta_generic_to_shared(smf);

    const int blk = blockIdx.x;
    const int b = blk >> 5;
    const int qbase = (blk & 31) * 128;
    const int tid = threadIdx.x;
    const int w = tid >> 5, l = tid & 31, g = l >> 2, t = l & 3;
    const int r1 = w * 16 + g;

    // per-thread swizzle constants
    const int pg  = (g ^ (g >> 1)) & 3;              // S-phase rows nt*8+g
    const int pr0 = ((2*t)     ^ t) & 3;             // PV b0 rows 8kt+2t
    const int pr1 = ((2*t + 1) ^ t) & 3;             // PV b1 rows 8kt+2t+1

    // Q fragments (permuted k: col t -> ch 8kt+2t, col t+4 -> ch 8kt+2t+1)
    const float* Qg = g_q + (size_t)(b * NTOK + qbase) * CH;
    unsigned qa[16][4];
    #pragma unroll
    for (int kt = 0; kt < 16; kt++) {
        float2 q0 = *(const float2*)&Qg[(size_t)r1       * CH + kt*8 + 2*t];
        float2 q1 = *(const float2*)&Qg[(size_t)(r1 + 8) * CH + kt*8 + 2*t];
        qa[kt][0] = f2tf(q0.x * ATT_SCALE);
        qa[kt][1] = f2tf(q1.x * ATT_SCALE);
        qa[kt][2] = f2tf(q0.y * ATT_SCALE);
        qa[kt][3] = f2tf(q1.y * ATT_SCALE);
    }

    float oacc[16][4];
    #pragma unroll
    for (int nt = 0; nt < 16; nt++)
        #pragma unroll
        for (int c = 0; c < 4; c++) oacc[nt][c] = 0.f;
    float m1 = -1e30f, m2 = -1e30f, l1 = 0.f, l2 = 0.f;

    const float* KgB = g_k + (size_t)b * NTOK * CH;
    const float* VgB = g_v + (size_t)b * NTOK * CH;

    // prime: stage tile 0 into buffer 0
    stage_tile(KgB, VgB, smem_base, smem_base + TILE_FLOATS * 4, tid);

    #pragma unroll 1
    for (int jt = 0; jt < 64; jt++) {
        if (jt < 63) {
            const uint32_t nb = smem_base + ((jt + 1) & 1) * (2 * TILE_FLOATS * 4);
            stage_tile(KgB + (size_t)(jt + 1) * 64 * CH,
                       VgB + (size_t)(jt + 1) * 64 * CH,
                       nb, nb + TILE_FLOATS * 4, tid);
            asm volatile("cp.async.wait_group 1;");
        } else {
            asm volatile("cp.async.wait_group 0;");
        }
        __syncthreads();                       // tile jt fully staged (all threads)

        const float* Kb = smf + (jt & 1) * (2 * TILE_FLOATS);
        const float* Vb = Kb + TILE_FLOATS;

        // ---- S = (Q*scale) @ K^T : 8 n-tiles of 8 keys ----
        float sacc[8][4];
        #pragma unroll
        for (int nt = 0; nt < 8; nt++)
            #pragma unroll
            for (int c = 0; c < 4; c++) sacc[nt][c] = 0.f;

        #pragma unroll
        for (int kt = 0; kt < 16; kt++) {
            const int co = 8 * (kt ^ pg) + 2 * t;      // swizzled ch offset
            #pragma unroll
            for (int nt = 0; nt < 8; nt++) {
                uint2 bb2 = *(const uint2*)&Kb[(nt*8 + g) * 128 + co];
                mma8(sacc[nt], qa[kt], bb2.x, bb2.y);
            }
        }

        // ---- online softmax (quad-local; keys 2t,2t+1 per n-tile) ----
        float mx1 = -1e30f, mx2 = -1e30f;
        #pragma unroll
        for (int nt = 0; nt < 8; nt++) {
            mx1 = fmaxf(mx1, fmaxf(sacc[nt][0], sacc[nt][1]));
            mx2 = fmaxf(mx2, fmaxf(sacc[nt][2], sacc[nt][3]));
        }
        #pragma unroll
        for (int off = 1; off < 4; off <<= 1) {
            mx1 = fmaxf(mx1, __shfl_xor_sync(0xffffffffu, mx1, off));
            mx2 = fmaxf(mx2, __shfl_xor_sync(0xffffffffu, mx2, off));
        }
        const float mn1 = fmaxf(m1, mx1), mn2 = fmaxf(m2, mx2);
        const float al1 = __expf(m1 - mn1), al2 = __expf(m2 - mn2);
        float rs1 = 0.f, rs2 = 0.f;
        #pragma unroll
        for (int nt = 0; nt < 8; nt++) {
            sacc[nt][0] = __expf(sacc[nt][0] - mn1);
            sacc[nt][1] = __expf(sacc[nt][1] - mn1);
            sacc[nt][2] = __expf(sacc[nt][2] - mn2);
            sacc[nt][3] = __expf(sacc[nt][3] - mn2);
            rs1 += sacc[nt][0] + sacc[nt][1];
            rs2 += sacc[nt][2] + sacc[nt][3];
        }
        #pragma unroll
        for (int off = 1; off < 4; off <<= 1) {
            rs1 += __shfl_xor_sync(0xffffffffu, rs1, off);
            rs2 += __shfl_xor_sync(0xffffffffu, rs2, off);
        }
        l1 = l1 * al1 + rs1;  l2 = l2 * al2 + rs2;
        m1 = mn1;  m2 = mn2;
        #pragma unroll
        for (int nt = 0; nt < 16; nt++) {
            oacc[nt][0] *= al1;  oacc[nt][1] *= al1;
            oacc[nt][2] *= al2;  oacc[nt][3] *= al2;
        }

        // ---- O += P @ V : P entirely in registers (permuted k) ----
        #pragma unroll
        for (int kt = 0; kt < 8; kt++) {
            unsigned ar[4] = {__float_as_uint(sacc[kt][0]),
                              __float_as_uint(sacc[kt][2]),
                              __float_as_uint(sacc[kt][1]),
                              __float_as_uint(sacc[kt][3])};
            const float* v0row = Vb + (8*kt + 2*t)     * 128;
            const float* v1row = Vb + (8*kt + 2*t + 1) * 128;
            #pragma unroll
            for (int nt = 0; nt < 16; nt++) {
                unsigned b0 = __float_as_uint(v0row[8 * (nt ^ pr0) + g]);
                unsigned b1 = __float_as_uint(v1row[8 * (nt ^ pr1) + g]);
                mma8(oacc[nt], ar, b0, b1);
            }
        }
        __syncthreads();                       // done reading buf[jt&1]
    }

    float* Og = g_attn + (size_t)(b * NTOK + qbase) * CH;
    const float inv1 = 1.0f / l1, inv2 = 1.0f / l2;
    #pragma unroll
    for (int nt = 0; nt < 16; nt++) {
        const int ch = nt * 8 + 2 * t;
        float2 v0 = {oacc[nt][0] * inv1, oacc[nt][1] * inv1};
        float2 v1 = {oacc[nt][2] * inv2, oacc[nt][3] * inv2};
        *(float2*)&Og[(size_t)r1 * CH + ch]       = v0;
        *(float2*)&Og[(size_t)(r1 + 8) * CH + ch] = v1;
    }
}

// ---------------------------------------------------------------------------
// K5: output projection via tf32 mma + bias + residual (unchanged from R6)
// ---------------------------------------------------------------------------
__global__ void __launch_bounds__(256) proj_mma(const float* __restrict__ W,
                                                const float* __restrict__ bias,
                                                float* __restrict__ out) {
    extern __shared__ unsigned Ws[];
    const int tid = threadIdx.x;
    const int w = tid >> 5, l = tid & 31, g = l >> 2, t = l & 3;

    #pragma unroll
    for (int o = 0; o < 2; o++) {
        const int n = o * 64 + w * 8 + g;
        #pragma unroll
        for (int i = 0; i < 16; i++) {
            unsigned v0 = f2tf(W[n * CH + i*8 + t]);
            unsigned v1 = f2tf(W[n * CH + i*8 + t + 4]);
            const int qs = (4*i + t) ^ ((n & 3) << 2);
            *(uint2*)&Ws[n * CH + 2 * qs] = make_uint2(v0, v1);
        }
    }
    __syncthreads();

    const int m0 = blockIdx.x * 128;
    const int gm = m0 + w * 16 + g;
    unsigned aa[16][4];
    #pragma unroll
    for (int kt = 0; kt < 16; kt++) {
        aa[kt][0] = f2tf(g_attn[(size_t)gm       * CH + kt*8 + t    ]);
        aa[kt][1] = f2tf(g_attn[(size_t)(gm + 8) * CH + kt*8 + t    ]);
        aa[kt][2] = f2tf(g_attn[(size_t)gm       * CH + kt*8 + t + 4]);
        aa[kt][3] = f2tf(g_attn[(size_t)(gm + 8) * CH + kt*8 + t + 4]);
    }

    float acc[16][4];
    #pragma unroll
    for (int nt = 0; nt < 16; nt++)
        #pragma unroll
        for (int c = 0; c < 4; c++) acc[nt][c] = 0.f;

    const int sw = (g & 3) << 2;
    #pragma unroll
    for (int kt = 0; kt < 16; kt++) {
        const int qs = (kt * 4 + t) ^ sw;
        #pragma unroll
        for (int nt = 0; nt < 16; nt++) {
            uint2 b = *(uint2*)&Ws[(nt*8 + g) * CH + 2 * qs];
            mma8(acc[nt], aa[kt], b.x, b.y);
        }
    }

    const int bb = m0 >> 12;
    const int tok = (m0 & (NTOK - 1)) + w * 16 + g;
    #pragma unroll
    for (int nt = 0; nt < 16; nt++) {
        #pragma unroll
        for (int c = 0; c < 2; c++) {
            const int ch = nt * 8 + 2 * t + c;
            const float bo = bias[ch];
            const size_t a0 = ((size_t)bb * CH + ch) * NTOK + tok;
            out[a0]     = acc[nt][c]     + bo + g_normed[a0];
            out[a0 + 8] = acc[nt][c + 2] + bo + g_normed[a0 + 8];
        }
    }
}

// ---------------------------------------------------------------------------
extern "C" void kernel_launch(void* const* d_in, const int* in_sizes, int n_in,
                              void* d_out, int out_size) {
    const float* x   = (const float*)d_in[0];
    const float* gnw = (const float*)d_in[1];
    const float* gnb = (const float*)d_in[2];
    const float* Wq  = (const float*)d_in[3];
    const float* bq  = (const float*)d_in[4];
    const float* Wk  = (const float*)d_in[5];
    const float* bk  = (const float*)d_in[6];
    const float* Wv  = (const float*)d_in[7];
    const float* bv  = (const float*)d_in[8];
    const float* Wp  = (const float*)d_in[9];
    const float* bp  = (const float*)d_in[10];
    float* out = (float*)d_out;

    cudaFuncSetAttribute(flash_mma, cudaFuncAttributeMaxDynamicSharedMemorySize, FL_SMEM_BYTES);
    cudaFuncSetAttribute(qkv_mma,  cudaFuncAttributeMaxDynamicSharedMemorySize, 65536);
    cudaFuncSetAttribute(proj_mma, cudaFuncAttributeMaxDynamicSharedMemorySize, 65536);

    gn_stats<<<BATCH * NGRP, 256>>>(x);
    gn_apply<<<(BATCH * CH * NTOK / 4) / 256, 256>>>(x, gnw, gnb);
    qkv_mma<<<dim3(BATCH * NTOK / 128, 3), 256, 65536>>>(Wq, bq, Wk, bk, Wv, bv);
    flash_mma<<<BATCH * (NTOK / 128), 256, FL_SMEM_BYTES>>>();
    proj_mma<<<BATCH * NTOK / 128, 256, 65536>>>(Wp, bp, out);
}

// round 9
// speedup vs baseline: 3.5658x; 1.1429x over previous
#include <cuda_runtime.h>
#include <math.h>
#include <stdint.h>

#define BATCH 8
#define CH 128
#define NTOK 4096          // H*W
#define NGRP 32
#define CPG 4
#define EPSV 1e-5f
#define ATT_SCALE 0.08838834764831845f        // 1/sqrt(128)
#define QSC (ATT_SCALE * 1.4426950408889634f) // fold log2(e): exp -> ex2

// scratch (static device globals; no allocation allowed)
__device__ float g_normed[BATCH*CH*NTOK];   // NCHW
__device__ float g_q[BATCH*NTOK*CH];        // token-major [b*N+n][c]
__device__ float g_k[BATCH*NTOK*CH];        // token-major
__device__ float g_v[BATCH*CH*NTOK];        // CHANNEL-major [b][c][n]  (R8)
__device__ float g_attn[BATCH*NTOK*CH];
__device__ float g_mean[BATCH*NGRP];
__device__ float g_rstd[BATCH*NGRP];

// ---------------------------------------------------------------------------
// helpers
// ---------------------------------------------------------------------------
__device__ __forceinline__ unsigned f2tf(float f) {
    unsigned r;
    asm("cvt.rna.tf32.f32 %0, %1;" : "=r"(r) : "f"(f));
    return r;
}
__device__ __forceinline__ float ex2(float x) {
    float r;
    asm("ex2.approx.ftz.f32 %0, %1;" : "=f"(r) : "f"(x));
    return r;
}
__device__ __forceinline__ void mma8(float* d, const unsigned* a, unsigned b0, unsigned b1) {
    asm volatile(
        "mma.sync.aligned.m16n8k8.row.col.f32.tf32.tf32.f32 "
        "{%0,%1,%2,%3}, {%4,%5,%6,%7}, {%8,%9}, {%0,%1,%2,%3};"
        : "+f"(d[0]), "+f"(d[1]), "+f"(d[2]), "+f"(d[3])
        : "r"(a[0]), "r"(a[1]), "r"(a[2]), "r"(a[3]), "r"(b0), "r"(b1));
}

// ---------------------------------------------------------------------------
// K1: GroupNorm statistics
// ---------------------------------------------------------------------------
__global__ void gn_stats(const float* __restrict__ x) {
    const int bg = blockIdx.x;
    const float4* p = (const float4*)(x + (size_t)bg * CPG * NTOK);
    const int n4 = CPG * NTOK / 4;
    float s = 0.f, s2 = 0.f;
    for (int i = threadIdx.x; i < n4; i += blockDim.x) {
        float4 v = p[i];
        s  += v.x + v.y + v.z + v.w;
        s2 += v.x*v.x + v.y*v.y + v.z*v.z + v.w*v.w;
    }
    __shared__ float ss[256], ss2[256];
    ss[threadIdx.x] = s; ss2[threadIdx.x] = s2;
    __syncthreads();
    for (int st = 128; st > 0; st >>= 1) {
        if (threadIdx.x < st) {
            ss[threadIdx.x]  += ss[threadIdx.x + st];
            ss2[threadIdx.x] += ss2[threadIdx.x + st];
        }
        __syncthreads();
    }
    if (threadIdx.x == 0) {
        const float invn = 1.0f / (CPG * NTOK);
        float mu  = ss[0] * invn;
        float var = ss2[0] * invn - mu * mu;
        g_mean[bg] = mu;
        g_rstd[bg] = rsqrtf(var + EPSV);
    }
}

// ---------------------------------------------------------------------------
// K2: apply GroupNorm
// ---------------------------------------------------------------------------
__global__ void gn_apply(const float* __restrict__ x,
                         const float* __restrict__ gw,
                         const float* __restrict__ gb) {
    const int idx = blockIdx.x * blockDim.x + threadIdx.x;
    const int c_lin = idx >> 10;
    const int c = c_lin & (CH - 1);
    const int bg = c_lin >> 2;
    const float mu = g_mean[bg], rs = g_rstd[bg];
    const float a = rs * gw[c];
    const float bb = gb[c] - mu * a;
    float4 v = ((const float4*)x)[idx];
    v.x = v.x * a + bb;  v.y = v.y * a + bb;
    v.z = v.z * a + bb;  v.w = v.w * a + bb;
    ((float4*)g_normed)[idx] = v;
}

// ---------------------------------------------------------------------------
// K3: QKV projections via tf32 mma. sel 0/1 -> token-major q/k;
// sel 2 -> V written CHANNEL-major (for lds.64 PV fragments in flash).
// ---------------------------------------------------------------------------
__global__ void __launch_bounds__(256) qkv_mma(
        const float* __restrict__ Wq, const float* __restrict__ bq,
        const float* __restrict__ Wk, const float* __restrict__ bk,
        const float* __restrict__ Wv, const float* __restrict__ bv) {
    extern __shared__ unsigned Ws[];
    const int tid = threadIdx.x;
    const int w = tid >> 5, l = tid & 31, g = l >> 2, t = l & 3;
    const int sel = blockIdx.y;
    const float* W    = (sel == 0) ? Wq : (sel == 1 ? Wk : Wv);
    const float* bias = (sel == 0) ? bq : (sel == 1 ? bk : bv);

    #pragma unroll
    for (int o = 0; o < 2; o++) {
        const int n = o * 64 + w * 8 + g;
        #pragma unroll
        for (int i = 0; i < 16; i++) {
            unsigned v0 = f2tf(W[n * CH + i * 8 + t]);
            unsigned v1 = f2tf(W[n * CH + i * 8 + t + 4]);
            const int qs = (4 * i + t) ^ ((n & 3) << 2);
            *(uint2*)&Ws[n * CH + 2 * qs] = make_uint2(v0, v1);
        }
    }
    __syncthreads();

    const int m0 = blockIdx.x * 128;
    const int bb = m0 >> 12;
    const int tok = (m0 & (NTOK - 1)) + w * 16 + g;
    const float* A = g_normed + (size_t)bb * CH * NTOK;

    unsigned aa[16][4];
    #pragma unroll
    for (int kt = 0; kt < 16; kt++) {
        aa[kt][0] = f2tf(A[(size_t)(kt*8 + t    ) * NTOK + tok    ]);
        aa[kt][1] = f2tf(A[(size_t)(kt*8 + t    ) * NTOK + tok + 8]);
        aa[kt][2] = f2tf(A[(size_t)(kt*8 + t + 4) * NTOK + tok    ]);
        aa[kt][3] = f2tf(A[(size_t)(kt*8 + t + 4) * NTOK + tok + 8]);
    }

    float acc[16][4];
    #pragma unroll
    for (int nt = 0; nt < 16; nt++)
        #pragma unroll
        for (int c = 0; c < 4; c++) acc[nt][c] = 0.f;

    const int sw = (g & 3) << 2;
    #pragma unroll
    for (int kt = 0; kt < 16; kt++) {
        const int qs = (kt * 4 + t) ^ sw;
        #pragma unroll
        for (int nt = 0; nt < 16; nt++) {
            uint2 b = *(uint2*)&Ws[(nt*8 + g) * CH + 2 * qs];
            mma8(acc[nt], aa[kt], b.x, b.y);
        }
    }

    const int gm = m0 + w * 16 + g;
    if (sel == 2) {
        // V: channel-major [b][c][n]
        const int n = gm & (NTOK - 1);
        float* outp = g_v;
        #pragma unroll
        for (int nt = 0; nt < 16; nt++) {
            #pragma unroll
            for (int c = 0; c < 2; c++) {
                const int ch = nt * 8 + 2 * t + c;
                const float bo = bias[ch];
                const size_t a0 = ((size_t)bb * CH + ch) * NTOK + n;
                outp[a0]     = acc[nt][c]     + bo;
                outp[a0 + 8] = acc[nt][c + 2] + bo;
            }
        }
    } else {
        float* outp = (sel == 0) ? g_q : g_k;
        #pragma unroll
        for (int nt = 0; nt < 16; nt++) {
            const int ch = nt * 8 + 2 * t;
            const float b0 = bias[ch], b1 = bias[ch + 1];
            float2 v0 = {acc[nt][0] + b0, acc[nt][1] + b1};
            float2 v1 = {acc[nt][2] + b0, acc[nt][3] + b1};
            *(float2*)&outp[(size_t)gm * CH + ch]       = v0;
            *(float2*)&outp[(size_t)(gm + 8) * CH + ch] = v1;
        }
    }
}

// ---------------------------------------------------------------------------
// K4: tf32 flash attention, v3.
//  K tile: [key 0..63][128 ch], 16B-chunk swizzle  c ^= (row&1)<<2
//    -> paired k-permutation: mma (m,j) covers chs {16m+4t+2j(+1)}; one
//       lds.128 feeds B-fragments of TWO mmas.
//  V tile: [ch 0..127][64 key], 16B-chunk swizzle  kc ^= (ch&3)<<1
//    -> PV B-fragment pair (keys 8kt+2t, +1) contiguous: lds.64.
//  softmax in exp2 domain (scale*log2e folded into Q); conditional rescale.
// ---------------------------------------------------------------------------
#define TILE_FLOATS 8192                       // 32KB per K or V tile
#define FL_SMEM_BYTES (4 * TILE_FLOATS * 4)    // K0,V0,K1,V1 = 128KB

__device__ __forceinline__ void stage_tile(const float* __restrict__ Kg,
                                           const float* __restrict__ Vt,
                                           uint32_t dK, uint32_t dV, int tid) {
    #pragma unroll
    for (int u = 0; u < 8; u++) {              // K: 64 rows x 32 chunks
        const int h = u * 256 + tid;
        const int row = h >> 5, c = h & 31;
        const uint32_t off = row * 512 + ((c ^ ((row & 1) << 2)) << 4);
        asm volatile("cp.async.cg.shared.global [%0], [%1], 16;"
                     :: "r"(dK + off), "l"(Kg + row * CH + c * 4));
    }
    #pragma unroll
    for (int u = 0; u < 8; u++) {              // V: 128 rows x 16 chunks
        const int h = u * 256 + tid;
        const int ch = h >> 4, kc = h & 15;
        const uint32_t off = ch * 256 + ((kc ^ ((ch & 3) << 1)) << 4);
        asm volatile("cp.async.cg.shared.global [%0], [%1], 16;"
                     :: "r"(dV + off), "l"(Vt + (size_t)ch * NTOK + kc * 4));
    }
    asm volatile("cp.async.commit_group;");
}

__global__ void __launch_bounds__(256) flash_mma() {
    extern __shared__ float smf[];
    const uint32_t smem_base = (uint32_t)__cvta_generic_to_shared(smf);

    const int blk = blockIdx.x;
    const int b = blk >> 5;
    const int qbase = (blk & 31) * 128;
    const int tid = threadIdx.x;
    const int w = tid >> 5, l = tid & 31, g = l >> 2, t = l & 3;
    const int r1 = w * 16 + g;

    const int ksw = (g & 1) << 2;              // K chunk swizzle term
    const int vsw = (g & 3) << 1;              // V chunk swizzle term
    const int pos = (2 * t) & 3;               // PV within-chunk offset

    // Q fragments, paired permutation: qa[2m+j] cols t,t+4 -> chs 16m+4t+2j(,+1)
    const float* Qg = g_q + (size_t)(b * NTOK + qbase) * CH;
    unsigned qa[16][4];
    #pragma unroll
    for (int m = 0; m < 8; m++) {
        float4 q0 = *(const float4*)&Qg[(size_t)r1       * CH + 16*m + 4*t];
        float4 q1 = *(const float4*)&Qg[(size_t)(r1 + 8) * CH + 16*m + 4*t];
        qa[2*m  ][0] = f2tf(q0.x * QSC);  qa[2*m  ][2] = f2tf(q0.y * QSC);
        qa[2*m+1][0] = f2tf(q0.z * QSC);  qa[2*m+1][2] = f2tf(q0.w * QSC);
        qa[2*m  ][1] = f2tf(q1.x * QSC);  qa[2*m  ][3] = f2tf(q1.y * QSC);
        qa[2*m+1][1] = f2tf(q1.z * QSC);  qa[2*m+1][3] = f2tf(q1.w * QSC);
    }

    float oacc[16][4];
    #pragma unroll
    for (int nt = 0; nt < 16; nt++)
        #pragma unroll
        for (int c = 0; c < 4; c++) oacc[nt][c] = 0.f;
    float m1 = -1e30f, m2 = -1e30f, l1 = 0.f, l2 = 0.f;

    const float* KgB = g_k + (size_t)b * NTOK * CH;       // [key][ch]
    const float* VgB = g_v + (size_t)b * CH * NTOK;       // [ch][key]

    stage_tile(KgB, VgB, smem_base, smem_base + TILE_FLOATS * 4, tid);

    #pragma unroll 1
    for (int jt = 0; jt < 64; jt++) {
        if (jt < 63) {
            const uint32_t nb = smem_base + ((jt + 1) & 1) * (2 * TILE_FLOATS * 4);
            stage_tile(KgB + (size_t)(jt + 1) * 64 * CH,
                       VgB + (size_t)(jt + 1) * 64,
                       nb, nb + TILE_FLOATS * 4, tid);
            asm volatile("cp.async.wait_group 1;");
        } else {
            asm volatile("cp.async.wait_group 0;");
        }
        __syncthreads();

        const float* Kb = smf + (jt & 1) * (2 * TILE_FLOATS);
        const float* Vb = Kb + TILE_FLOATS;

        // ---- S = (Q*qsc) @ K^T : one lds.128 -> 2 mmas ----
        float sacc[8][4];
        #pragma unroll
        for (int nt = 0; nt < 8; nt++)
            #pragma unroll
            for (int c = 0; c < 4; c++) sacc[nt][c] = 0.f;

        #pragma unroll
        for (int m = 0; m < 8; m++) {
            const int co = 4 * ((4*m + t) ^ ksw);
            #pragma unroll
            for (int nt = 0; nt < 8; nt++) {
                const uint4 kv = *(const uint4*)&Kb[(nt*8 + g) * 128 + co];
                mma8(sacc[nt], qa[2*m],   kv.x, kv.y);
                mma8(sacc[nt], qa[2*m+1], kv.z, kv.w);
            }
        }

        // ---- online softmax, exp2 domain (quad-local) ----
        float mx1 = -1e30f, mx2 = -1e30f;
        #pragma unroll
        for (int nt = 0; nt < 8; nt++) {
            mx1 = fmaxf(mx1, fmaxf(sacc[nt][0], sacc[nt][1]));
            mx2 = fmaxf(mx2, fmaxf(sacc[nt][2], sacc[nt][3]));
        }
        #pragma unroll
        for (int off = 1; off < 4; off <<= 1) {
            mx1 = fmaxf(mx1, __shfl_xor_sync(0xffffffffu, mx1, off));
            mx2 = fmaxf(mx2, __shfl_xor_sync(0xffffffffu, mx2, off));
        }
        const float mn1 = fmaxf(m1, mx1), mn2 = fmaxf(m2, mx2);
        const float al1 = ex2(m1 - mn1), al2 = ex2(m2 - mn2);
        float rs1 = 0.f, rs2 = 0.f;
        #pragma unroll
        for (int nt = 0; nt < 8; nt++) {
            sacc[nt][0] = ex2(sacc[nt][0] - mn1);
            sacc[nt][1] = ex2(sacc[nt][1] - mn1);
            sacc[nt][2] = ex2(sacc[nt][2] - mn2);
            sacc[nt][3] = ex2(sacc[nt][3] - mn2);
            rs1 += sacc[nt][0] + sacc[nt][1];
            rs2 += sacc[nt][2] + sacc[nt][3];
        }
        #pragma unroll
        for (int off = 1; off < 4; off <<= 1) {
            rs1 += __shfl_xor_sync(0xffffffffu, rs1, off);
            rs2 += __shfl_xor_sync(0xffffffffu, rs2, off);
        }
        l1 = l1 * al1 + rs1;  l2 = l2 * al2 + rs2;
        m1 = mn1;  m2 = mn2;
        const bool noresc = __all_sync(0xffffffffu, (al1 == 1.0f) && (al2 == 1.0f));
        if (!noresc) {
            #pragma unroll
            for (int nt = 0; nt < 16; nt++) {
                oacc[nt][0] *= al1;  oacc[nt][1] *= al1;
                oacc[nt][2] *= al2;  oacc[nt][3] *= al2;
            }
        }

        // ---- O += P @ V : P in registers; V pairs via lds.64 ----
        #pragma unroll
        for (int kt = 0; kt < 8; kt++) {
            unsigned ar[4] = {__float_as_uint(sacc[kt][0]),
                              __float_as_uint(sacc[kt][2]),
                              __float_as_uint(sacc[kt][1]),
                              __float_as_uint(sacc[kt][3])};
            const int kc0 = 2*kt + (t >> 1);
            const int koff = 4 * (kc0 ^ vsw) + pos;
            #pragma unroll
            for (int nt = 0; nt < 16; nt++) {
                const uint2 vv = *(const uint2*)&Vb[(nt*8 + g) * 64 + koff];
                mma8(oacc[nt], ar, vv.x, vv.y);
            }
        }
        __syncthreads();
    }

    float* Og = g_attn + (size_t)(b * NTOK + qbase) * CH;
    const float inv1 = 1.0f / l1, inv2 = 1.0f / l2;
    #pragma unroll
    for (int nt = 0; nt < 16; nt++) {
        const int ch = nt * 8 + 2 * t;
        float2 v0 = {oacc[nt][0] * inv1, oacc[nt][1] * inv1};
        float2 v1 = {oacc[nt][2] * inv2, oacc[nt][3] * inv2};
        *(float2*)&Og[(size_t)r1 * CH + ch]       = v0;
        *(float2*)&Og[(size_t)(r1 + 8) * CH + ch] = v1;
    }
}

// ---------------------------------------------------------------------------
// K5: output projection via tf32 mma + bias + residual (unchanged)
// ---------------------------------------------------------------------------
__global__ void __launch_bounds__(256) proj_mma(const float* __restrict__ W,
                                                const float* __restrict__ bias,
                                                float* __restrict__ out) {
    extern __shared__ unsigned Ws[];
    const int tid = threadIdx.x;
    const int w = tid >> 5, l = tid & 31, g = l >> 2, t = l & 3;

    #pragma unroll
    for (int o = 0; o < 2; o++) {
        const int n = o * 64 + w * 8 + g;
        #pragma unroll
        for (int i = 0; i < 16; i++) {
            unsigned v0 = f2tf(W[n * CH + i*8 + t]);
            unsigned v1 = f2tf(W[n * CH + i*8 + t + 4]);
            const int qs = (4*i + t) ^ ((n & 3) << 2);
            *(uint2*)&Ws[n * CH + 2 * qs] = make_uint2(v0, v1);
        }
    }
    __syncthreads();

    const int m0 = blockIdx.x * 128;
    const int gm = m0 + w * 16 + g;
    unsigned aa[16][4];
    #pragma unroll
    for (int kt = 0; kt < 16; kt++) {
        aa[kt][0] = f2tf(g_attn[(size_t)gm       * CH + kt*8 + t    ]);
        aa[kt][1] = f2tf(g_attn[(size_t)(gm + 8) * CH + kt*8 + t    ]);
        aa[kt][2] = f2tf(g_attn[(size_t)gm       * CH + kt*8 + t + 4]);
        aa[kt][3] = f2tf(g_attn[(size_t)(gm + 8) * CH + kt*8 + t + 4]);
    }

    float acc[16][4];
    #pragma unroll
    for (int nt = 0; nt < 16; nt++)
        #pragma unroll
        for (int c = 0; c < 4; c++) acc[nt][c] = 0.f;

    const int sw = (g & 3) << 2;
    #pragma unroll
    for (int kt = 0; kt < 16; kt++) {
        const int qs = (kt * 4 + t) ^ sw;
        #pragma unroll
        for (int nt = 0; nt < 16; nt++) {
            uint2 b = *(uint2*)&Ws[(nt*8 + g) * CH + 2 * qs];
            mma8(acc[nt], aa[kt], b.x, b.y);
        }
    }

    const int bb = m0 >> 12;
    const int tok = (m0 & (NTOK - 1)) + w * 16 + g;
    #pragma unroll
    for (int nt = 0; nt < 16; nt++) {
        #pragma unroll
        for (int c = 0; c < 2; c++) {
            const int ch = nt * 8 + 2 * t + c;
            const float bo = bias[ch];
            const size_t a0 = ((size_t)bb * CH + ch) * NTOK + tok;
            out[a0]     = acc[nt][c]     + bo + g_normed[a0];
            out[a0 + 8] = acc[nt][c + 2] + bo + g_normed[a0 + 8];
        }
    }
}

// ---------------------------------------------------------------------------
extern "C" void kernel_launch(void* const* d_in, const int* in_sizes, int n_in,
                              void* d_out, int out_size) {
    const float* x   = (const float*)d_in[0];
    const float* gnw = (const float*)d_in[1];
    const float* gnb = (const float*)d_in[2];
    const float* Wq  = (const float*)d_in[3];
    const float* bq  = (const float*)d_in[4];
    const float* Wk  = (const float*)d_in[5];
    const float* bk  = (const float*)d_in[6];
    const float* Wv  = (const float*)d_in[7];
    const float* bv  = (const float*)d_in[8];
    const float* Wp  = (const float*)d_in[9];
    const float* bp  = (const float*)d_in[10];
    float* out = (float*)d_out;

    cudaFuncSetAttribute(flash_mma, cudaFuncAttributeMaxDynamicSharedMemorySize, FL_SMEM_BYTES);
    cudaFuncSetAttribute(qkv_mma,  cudaFuncAttributeMaxDynamicSharedMemorySize, 65536);
    cudaFuncSetAttribute(proj_mma, cudaFuncAttributeMaxDynamicSharedMemorySize, 65536);

    gn_stats<<<BATCH * NGRP, 256>>>(x);
    gn_apply<<<(BATCH * CH * NTOK / 4) / 256, 256>>>(x, gnw, gnb);
    qkv_mma<<<dim3(BATCH * NTOK / 128, 3), 256, 65536>>>(Wq, bq, Wk, bk, Wv, bv);
    flash_mma<<<BATCH * (NTOK / 128), 256, FL_SMEM_BYTES>>>();
    proj_mma<<<BATCH * NTOK / 128, 256, 65536>>>(Wp, bp, out);
}

// round 10
// speedup vs baseline: 5.3210x; 1.4923x over previous
#include <cuda_runtime.h>
#include <cuda_bf16.h>
#include <math.h>
#include <stdint.h>

#define BATCH 8
#define CH 128
#define NTOK 4096          // H*W
#define NGRP 32
#define CPG 4
#define EPSV 1e-5f
#define ATT_SCALE 0.08838834764831845f        // 1/sqrt(128)
#define QSC (ATT_SCALE * 1.4426950408889634f) // fold log2(e): exp -> ex2

// scratch (static device globals; no allocation allowed)
__device__ float g_normed[BATCH*CH*NTOK];            // NCHW
__device__ float g_q[BATCH*NTOK*CH];                 // token-major, CH-permuted
__device__ __nv_bfloat16 g_kb[BATCH*NTOK*CH];        // token-major, CH-permuted
__device__ __nv_bfloat16 g_vb[BATCH*CH*NTOK];        // channel-major, key-permuted
__device__ float g_attn[BATCH*NTOK*CH];
__device__ float g_mean[BATCH*NGRP];
__device__ float g_rstd[BATCH*NGRP];

// ---------------------------------------------------------------------------
// helpers
// ---------------------------------------------------------------------------
__device__ __forceinline__ unsigned f2tf(float f) {
    unsigned r;
    asm("cvt.rna.tf32.f32 %0, %1;" : "=r"(r) : "f"(f));
    return r;
}
__device__ __forceinline__ float ex2(float x) {
    float r;
    asm("ex2.approx.ftz.f32 %0, %1;" : "=f"(r) : "f"(x));
    return r;
}
// pack (lo, hi) floats into bf16x2 register (lo in low half)
__device__ __forceinline__ unsigned bfpack(float lo, float hi) {
    unsigned d;
    asm("cvt.rn.bf16x2.f32 %0, %1, %2;" : "=r"(d) : "f"(hi), "f"(lo));
    return d;
}
// tf32 m16n8k8 (used by qkv/proj, unchanged)
__device__ __forceinline__ void mma8(float* d, const unsigned* a, unsigned b0, unsigned b1) {
    asm volatile(
        "mma.sync.aligned.m16n8k8.row.col.f32.tf32.tf32.f32 "
        "{%0,%1,%2,%3}, {%4,%5,%6,%7}, {%8,%9}, {%0,%1,%2,%3};"
        : "+f"(d[0]), "+f"(d[1]), "+f"(d[2]), "+f"(d[3])
        : "r"(a[0]), "r"(a[1]), "r"(a[2]), "r"(a[3]), "r"(b0), "r"(b1));
}
// bf16 m16n8k16 (flash)
__device__ __forceinline__ void mma16(float* d, const unsigned* a, unsigned b0, unsigned b1) {
    asm volatile(
        "mma.sync.aligned.m16n8k16.row.col.f32.bf16.bf16.f32 "
        "{%0,%1,%2,%3}, {%4,%5,%6,%7}, {%8,%9}, {%0,%1,%2,%3};"
        : "+f"(d[0]), "+f"(d[1]), "+f"(d[2]), "+f"(d[3])
        : "r"(a[0]), "r"(a[1]), "r"(a[2]), "r"(a[3]), "r"(b0), "r"(b1));
}

// ---------------------------------------------------------------------------
// K1: GroupNorm statistics
// ---------------------------------------------------------------------------
__global__ void gn_stats(const float* __restrict__ x) {
    const int bg = blockIdx.x;
    const float4* p = (const float4*)(x + (size_t)bg * CPG * NTOK);
    const int n4 = CPG * NTOK / 4;
    float s = 0.f, s2 = 0.f;
    for (int i = threadIdx.x; i < n4; i += blockDim.x) {
        float4 v = p[i];
        s  += v.x + v.y + v.z + v.w;
        s2 += v.x*v.x + v.y*v.y + v.z*v.z + v.w*v.w;
    }
    __shared__ float ss[256], ss2[256];
    ss[threadIdx.x] = s; ss2[threadIdx.x] = s2;
    __syncthreads();
    for (int st = 128; st > 0; st >>= 1) {
        if (threadIdx.x < st) {
            ss[threadIdx.x]  += ss[threadIdx.x + st];
            ss2[threadIdx.x] += ss2[threadIdx.x + st];
        }
        __syncthreads();
    }
    if (threadIdx.x == 0) {
        const float invn = 1.0f / (CPG * NTOK);
        float mu  = ss[0] * invn;
        float var = ss2[0] * invn - mu * mu;
        g_mean[bg] = mu;
        g_rstd[bg] = rsqrtf(var + EPSV);
    }
}

// ---------------------------------------------------------------------------
// K2: apply GroupNorm
// ---------------------------------------------------------------------------
__global__ void gn_apply(const float* __restrict__ x,
                         const float* __restrict__ gw,
                         const float* __restrict__ gb) {
    const int idx = blockIdx.x * blockDim.x + threadIdx.x;
    const int c_lin = idx >> 10;
    const int c = c_lin & (CH - 1);
    const int bg = c_lin >> 2;
    const float mu = g_mean[bg], rs = g_rstd[bg];
    const float a = rs * gw[c];
    const float bb = gb[c] - mu * a;
    float4 v = ((const float4*)x)[idx];
    v.x = v.x * a + bb;  v.y = v.y * a + bb;
    v.z = v.z * a + bb;  v.w = v.w * a + bb;
    ((float4*)g_normed)[idx] = v;
}

// ---------------------------------------------------------------------------
// K3: QKV projections via tf32 mma.
//  sel 0: Q fp32, token-major, channel-PERMUTED (within-16 group: logical
//         (2t,2t+1,8+2t,8+2t+1) -> physical (4t..4t+3))
//  sel 1: K bf16, token-major, same channel permutation
//  sel 2: V bf16, channel-major [b][c][n], token index PERMUTED within 16
// ---------------------------------------------------------------------------
__global__ void __launch_bounds__(256) qkv_mma(
        const float* __restrict__ Wq, const float* __restrict__ bq,
        const float* __restrict__ Wk, const float* __restrict__ bk,
        const float* __restrict__ Wv, const float* __restrict__ bv) {
    extern __shared__ unsigned Ws[];
    const int tid = threadIdx.x;
    const int w = tid >> 5, l = tid & 31, g = l >> 2, t = l & 3;
    const int sel = blockIdx.y;
    const float* W    = (sel == 0) ? Wq : (sel == 1 ? Wk : Wv);
    const float* bias = (sel == 0) ? bq : (sel == 1 ? bk : bv);

    #pragma unroll
    for (int o = 0; o < 2; o++) {
        const int n = o * 64 + w * 8 + g;
        #pragma unroll
        for (int i = 0; i < 16; i++) {
            unsigned v0 = f2tf(W[n * CH + i * 8 + t]);
            unsigned v1 = f2tf(W[n * CH + i * 8 + t + 4]);
            const int qs = (4 * i + t) ^ ((n & 3) << 2);
            *(uint2*)&Ws[n * CH + 2 * qs] = make_uint2(v0, v1);
        }
    }
    __syncthreads();

    const int m0 = blockIdx.x * 128;
    const int bb = m0 >> 12;
    const int tok = (m0 & (NTOK - 1)) + w * 16 + g;
    const float* A = g_normed + (size_t)bb * CH * NTOK;

    unsigned aa[16][4];
    #pragma unroll
    for (int kt = 0; kt < 16; kt++) {
        aa[kt][0] = f2tf(A[(size_t)(kt*8 + t    ) * NTOK + tok    ]);
        aa[kt][1] = f2tf(A[(size_t)(kt*8 + t    ) * NTOK + tok + 8]);
        aa[kt][2] = f2tf(A[(size_t)(kt*8 + t + 4) * NTOK + tok    ]);
        aa[kt][3] = f2tf(A[(size_t)(kt*8 + t + 4) * NTOK + tok + 8]);
    }

    float acc[16][4];
    #pragma unroll
    for (int nt = 0; nt < 16; nt++)
        #pragma unroll
        for (int c = 0; c < 4; c++) acc[nt][c] = 0.f;

    const int sw = (g & 3) << 2;
    #pragma unroll
    for (int kt = 0; kt < 16; kt++) {
        const int qs = (kt * 4 + t) ^ sw;
        #pragma unroll
        for (int nt = 0; nt < 16; nt++) {
            uint2 b = *(uint2*)&Ws[(nt*8 + g) * CH + 2 * qs];
            mma8(acc[nt], aa[kt], b.x, b.y);
        }
    }

    const int gm = m0 + w * 16 + g;
    if (sel == 0) {
        // Q fp32, channel-permuted: logical ch nt*8+2t(+1) -> phys 16a+4t+2h(+1)
        #pragma unroll
        for (int nt = 0; nt < 16; nt++) {
            const int chl = nt * 8 + 2 * t;
            const float b0 = bias[chl], b1 = bias[chl + 1];
            const int phys = (nt >> 1) * 16 + 4 * t + (nt & 1) * 2;
            float2 v0 = {acc[nt][0] + b0, acc[nt][1] + b1};
            float2 v1 = {acc[nt][2] + b0, acc[nt][3] + b1};
            *(float2*)&g_q[(size_t)gm * CH + phys]       = v0;
            *(float2*)&g_q[(size_t)(gm + 8) * CH + phys] = v1;
        }
    } else if (sel == 1) {
        // K bf16, channel-permuted
        #pragma unroll
        for (int nt = 0; nt < 16; nt++) {
            const int chl = nt * 8 + 2 * t;
            const float b0 = bias[chl], b1 = bias[chl + 1];
            const int phys = (nt >> 1) * 16 + 4 * t + (nt & 1) * 2;
            __nv_bfloat162 v0, v1;
            v0.x = __float2bfloat16(acc[nt][0] + b0);
            v0.y = __float2bfloat16(acc[nt][1] + b1);
            v1.x = __float2bfloat16(acc[nt][2] + b0);
            v1.y = __float2bfloat16(acc[nt][3] + b1);
            *(__nv_bfloat162*)&g_kb[(size_t)gm * CH + phys]       = v0;
            *(__nv_bfloat162*)&g_kb[(size_t)(gm + 8) * CH + phys] = v1;
        }
    } else {
        // V bf16 channel-major, token-permuted within 16:
        // local token g -> pg0 = 4*(g>>1)+(g&1); token g+8 -> pg0+2
        const int tloc = gm & (NTOK - 1);
        const int base16 = tloc - g;
        const int pg0 = 4 * (g >> 1) + (g & 1);
        #pragma unroll
        for (int nt = 0; nt < 16; nt++) {
            #pragma unroll
            for (int c = 0; c < 2; c++) {
                const int ch = nt * 8 + 2 * t + c;
                const float bo = bias[ch];
                const size_t a0 = ((size_t)bb * CH + ch) * NTOK + base16 + pg0;
                g_vb[a0]     = __float2bfloat16(acc[nt][c]     + bo);
                g_vb[a0 + 2] = __float2bfloat16(acc[nt][c + 2] + bo);
            }
        }
    }
}

// ---------------------------------------------------------------------------
// K4: bf16 m16n8k16 flash attention.
//  K tile: [64 key][128 ch] bf16 (256B/row); 32B ch-groups rotated by (m+row)&7
//  V tile: [128 ch][64 key] bf16 (128B/row); 32B key-groups rotated by (kt+row)&3
//  Rotations preserve 16B chunks (cp.async-compatible) and make every
//  B-fragment lds.64 conflict-free. P stays in registers (cvt to bf16x2).
// ---------------------------------------------------------------------------
#define KTILE_B 16384                          // 64*128*2
#define VTILE_B 16384                          // 128*64*2
#define FL_SMEM_BYTES (2 * (KTILE_B + VTILE_B))  // 64KB double-buffered

__device__ __forceinline__ void stage_tile(const __nv_bfloat16* __restrict__ Kg,
                                           const __nv_bfloat16* __restrict__ Vt,
                                           uint32_t dK, uint32_t dV, int tid) {
    #pragma unroll
    for (int u = 0; u < 4; u++) {              // K: 64 rows x 16 chunks(16B)
        const int h = u * 256 + tid;
        const int row = h >> 4, c = h & 15;
        const int c2 = ((((c >> 1) + row) & 7) << 1) | (c & 1);
        asm volatile("cp.async.cg.shared.global [%0], [%1], 16;"
                     :: "r"(dK + row * 256 + c2 * 16), "l"(Kg + row * CH + c * 8));
    }
    #pragma unroll
    for (int u = 0; u < 4; u++) {              // V: 128 rows x 8 chunks(16B)
        const int h = u * 256 + tid;
        const int row = h >> 3, c = h & 7;
        const int c2 = ((((c >> 1) + row) & 3) << 1) | (c & 1);
        asm volatile("cp.async.cg.shared.global [%0], [%1], 16;"
                     :: "r"(dV + row * 128 + c2 * 16), "l"(Vt + (size_t)row * NTOK + c * 8));
    }
    asm volatile("cp.async.commit_group;");
}

__global__ void __launch_bounds__(256) flash_mma() {
    extern __shared__ char smc[];
    const uint32_t smem_base = (uint32_t)__cvta_generic_to_shared(smc);

    const int blk = blockIdx.x;
    const int b = blk >> 5;
    const int qbase = (blk & 31) * 128;
    const int tid = threadIdx.x;
    const int w = tid >> 5, l = tid & 31, g = l >> 2, t = l & 3;
    const int r1 = w * 16 + g;

    // Q fragments: permuted g_q -> float4 = logical (2t,2t+1,8+2t,8+2t+1)
    const float* Qg = g_q + (size_t)(b * NTOK + qbase) * CH;
    unsigned qa[8][4];
    #pragma unroll
    for (int m = 0; m < 8; m++) {
        float4 F0 = *(const float4*)&Qg[(size_t)r1       * CH + m*16 + 4*t];
        float4 F1 = *(const float4*)&Qg[(size_t)(r1 + 8) * CH + m*16 + 4*t];
        qa[m][0] = bfpack(F0.x * QSC, F0.y * QSC);
        qa[m][1] = bfpack(F1.x * QSC, F1.y * QSC);
        qa[m][2] = bfpack(F0.z * QSC, F0.w * QSC);
        qa[m][3] = bfpack(F1.z * QSC, F1.w * QSC);
    }

    float oacc[16][4];
    #pragma unroll
    for (int nt = 0; nt < 16; nt++)
        #pragma unroll
        for (int c = 0; c < 4; c++) oacc[nt][c] = 0.f;
    float m1 = -1e30f, m2 = -1e30f, l1 = 0.f, l2 = 0.f;

    const __nv_bfloat16* KgB = g_kb + (size_t)b * NTOK * CH;   // [key][ch]
    const __nv_bfloat16* VgB = g_vb + (size_t)b * CH * NTOK;   // [ch][key]

    stage_tile(KgB, VgB, smem_base, smem_base + KTILE_B, tid);

    #pragma unroll 1
    for (int jt = 0; jt < 64; jt++) {
        if (jt < 63) {
            const uint32_t nb = smem_base + ((jt + 1) & 1) * (KTILE_B + VTILE_B);
            stage_tile(KgB + (size_t)(jt + 1) * 64 * CH,
                       VgB + (size_t)(jt + 1) * 64,
                       nb, nb + KTILE_B, tid);
            asm volatile("cp.async.wait_group 1;");
        } else {
            asm volatile("cp.async.wait_group 0;");
        }
        __syncthreads();

        const __nv_bfloat16* Kb =
            (const __nv_bfloat16*)(smc + (jt & 1) * (KTILE_B + VTILE_B));
        const __nv_bfloat16* Vb = Kb + KTILE_B / 2;

        // ---- S = (Q*qsc) @ K^T : 8 m-groups(k=16) x 8 nt, lds.64 B frags ----
        float sacc[8][4];
        #pragma unroll
        for (int nt = 0; nt < 8; nt++)
            #pragma unroll
            for (int c = 0; c < 4; c++) sacc[nt][c] = 0.f;

        #pragma unroll
        for (int m = 0; m < 8; m++) {
            const int moff = ((m + g) & 7) * 16 + 4 * t;
            #pragma unroll
            for (int nt = 0; nt < 8; nt++) {
                const uint2 kv = *(const uint2*)&Kb[(nt*8 + g) * 128 + moff];
                mma16(sacc[nt], qa[m], kv.x, kv.y);
            }
        }

        // ---- online softmax, exp2 domain (quad-local) ----
        float mx1 = -1e30f, mx2 = -1e30f;
        #pragma unroll
        for (int nt = 0; nt < 8; nt++) {
            mx1 = fmaxf(mx1, fmaxf(sacc[nt][0], sacc[nt][1]));
            mx2 = fmaxf(mx2, fmaxf(sacc[nt][2], sacc[nt][3]));
        }
        #pragma unroll
        for (int off = 1; off < 4; off <<= 1) {
            mx1 = fmaxf(mx1, __shfl_xor_sync(0xffffffffu, mx1, off));
            mx2 = fmaxf(mx2, __shfl_xor_sync(0xffffffffu, mx2, off));
        }
        const float mn1 = fmaxf(m1, mx1), mn2 = fmaxf(m2, mx2);
        const float al1 = ex2(m1 - mn1), al2 = ex2(m2 - mn2);
        float rs1 = 0.f, rs2 = 0.f;
        #pragma unroll
        for (int nt = 0; nt < 8; nt++) {
            sacc[nt][0] = ex2(sacc[nt][0] - mn1);
            sacc[nt][1] = ex2(sacc[nt][1] - mn1);
            sacc[nt][2] = ex2(sacc[nt][2] - mn2);
            sacc[nt][3] = ex2(sacc[nt][3] - mn2);
            rs1 += sacc[nt][0] + sacc[nt][1];
            rs2 += sacc[nt][2] + sacc[nt][3];
        }
        #pragma unroll
        for (int off = 1; off < 4; off <<= 1) {
            rs1 += __shfl_xor_sync(0xffffffffu, rs1, off);
            rs2 += __shfl_xor_sync(0xffffffffu, rs2, off);
        }
        l1 = l1 * al1 + rs1;  l2 = l2 * al2 + rs2;
        m1 = mn1;  m2 = mn2;
        const bool noresc = __all_sync(0xffffffffu, (al1 == 1.0f) && (al2 == 1.0f));
        if (!noresc) {
            #pragma unroll
            for (int nt = 0; nt < 16; nt++) {
                oacc[nt][0] *= al1;  oacc[nt][1] *= al1;
                oacc[nt][2] *= al2;  oacc[nt][3] *= al2;
            }
        }

        // ---- O += P @ V : 4 k-groups(16 keys) x 16 nt; P from sacc regs ----
        #pragma unroll
        for (int kt = 0; kt < 4; kt++) {
            unsigned ar[4];
            ar[0] = bfpack(sacc[2*kt    ][0], sacc[2*kt    ][1]);
            ar[1] = bfpack(sacc[2*kt    ][2], sacc[2*kt    ][3]);
            ar[2] = bfpack(sacc[2*kt + 1][0], sacc[2*kt + 1][1]);
            ar[3] = bfpack(sacc[2*kt + 1][2], sacc[2*kt + 1][3]);
            const int koff = ((kt + g) & 3) * 16 + 4 * t;
            #pragma unroll
            for (int nt = 0; nt < 16; nt++) {
                const uint2 vv = *(const uint2*)&Vb[(nt*8 + g) * 64 + koff];
                mma16(oacc[nt], ar, vv.x, vv.y);
            }
        }
        __syncthreads();
    }

    float* Og = g_attn + (size_t)(b * NTOK + qbase) * CH;
    const float inv1 = 1.0f / l1, inv2 = 1.0f / l2;
    #pragma unroll
    for (int nt = 0; nt < 16; nt++) {
        const int ch = nt * 8 + 2 * t;
        float2 v0 = {oacc[nt][0] * inv1, oacc[nt][1] * inv1};
        float2 v1 = {oacc[nt][2] * inv2, oacc[nt][3] * inv2};
        *(float2*)&Og[(size_t)r1 * CH + ch]       = v0;
        *(float2*)&Og[(size_t)(r1 + 8) * CH + ch] = v1;
    }
}

// ---------------------------------------------------------------------------
// K5: output projection via tf32 mma + bias + residual (unchanged)
// ---------------------------------------------------------------------------
__global__ void __launch_bounds__(256) proj_mma(const float* __restrict__ W,
                                                const float* __restrict__ bias,
                                                float* __restrict__ out) {
    extern __shared__ unsigned Ws[];
    const int tid = threadIdx.x;
    const int w = tid >> 5, l = tid & 31, g = l >> 2, t = l & 3;

    #pragma unroll
    for (int o = 0; o < 2; o++) {
        const int n = o * 64 + w * 8 + g;
        #pragma unroll
        for (int i = 0; i < 16; i++) {
            unsigned v0 = f2tf(W[n * CH + i*8 + t]);
            unsigned v1 = f2tf(W[n * CH + i*8 + t + 4]);
            const int qs = (4*i + t) ^ ((n & 3) << 2);
            *(uint2*)&Ws[n * CH + 2 * qs] = make_uint2(v0, v1);
        }
    }
    __syncthreads();

    const int m0 = blockIdx.x * 128;
    const int gm = m0 + w * 16 + g;
    unsigned aa[16][4];
    #pragma unroll
    for (int kt = 0; kt < 16; kt++) {
        aa[kt][0] = f2tf(g_attn[(size_t)gm       * CH + kt*8 + t    ]);
        aa[kt][1] = f2tf(g_attn[(size_t)(gm + 8) * CH + kt*8 + t    ]);
        aa[kt][2] = f2tf(g_attn[(size_t)gm       * CH + kt*8 + t + 4]);
        aa[kt][3] = f2tf(g_attn[(size_t)(gm + 8) * CH + kt*8 + t + 4]);
    }

    float acc[16][4];
    #pragma unroll
    for (int nt = 0; nt < 16; nt++)
        #pragma unroll
        for (int c = 0; c < 4; c++) acc[nt][c] = 0.f;

    const int sw = (g & 3) << 2;
    #pragma unroll
    for (int kt = 0; kt < 16; kt++) {
        const int qs = (kt * 4 + t) ^ sw;
        #pragma unroll
        for (int nt = 0; nt < 16; nt++) {
            uint2 b = *(uint2*)&Ws[(nt*8 + g) * CH + 2 * qs];
            mma8(acc[nt], aa[kt], b.x, b.y);
        }
    }

    const int bb = m0 >> 12;
    const int tok = (m0 & (NTOK - 1)) + w * 16 + g;
    #pragma unroll
    for (int nt = 0; nt < 16; nt++) {
        #pragma unroll
        for (int c = 0; c < 2; c++) {
            const int ch = nt * 8 + 2 * t + c;
            const float bo = bias[ch];
            const size_t a0 = ((size_t)bb * CH + ch) * NTOK + tok;
            out[a0]     = acc[nt][c]     + bo + g_normed[a0];
            out[a0 + 8] = acc[nt][c + 2] + bo + g_normed[a0 + 8];
        }
    }
}

// ---------------------------------------------------------------------------
extern "C" void kernel_launch(void* const* d_in, const int* in_sizes, int n_in,
                              void* d_out, int out_size) {
    const float* x   = (const float*)d_in[0];
    const float* gnw = (const float*)d_in[1];
    const float* gnb = (const float*)d_in[2];
    const float* Wq  = (const float*)d_in[3];
    const float* bq  = (const float*)d_in[4];
    const float* Wk  = (const float*)d_in[5];
    const float* bk  = (const float*)d_in[6];
    const float* Wv  = (const float*)d_in[7];
    const float* bv  = (const float*)d_in[8];
    const float* Wp  = (const float*)d_in[9];
    const float* bp  = (const float*)d_in[10];
    float* out = (float*)d_out;

    cudaFuncSetAttribute(flash_mma, cudaFuncAttributeMaxDynamicSharedMemorySize, FL_SMEM_BYTES);
    cudaFuncSetAttribute(qkv_mma,  cudaFuncAttributeMaxDynamicSharedMemorySize, 65536);
    cudaFuncSetAttribute(proj_mma, cudaFuncAttributeMaxDynamicSharedMemorySize, 65536);

    gn_stats<<<BATCH * NGRP, 256>>>(x);
    gn_apply<<<(BATCH * CH * NTOK / 4) / 256, 256>>>(x, gnw, gnb);
    qkv_mma<<<dim3(BATCH * NTOK / 128, 3), 256, 65536>>>(Wq, bq, Wk, bk, Wv, bv);
    flash_mma<<<BATCH * (NTOK / 128), 256, FL_SMEM_BYTES>>>();
    proj_mma<<<BATCH * NTOK / 128, 256, 65536>>>(Wp, bp, out);
}

// round 12
// speedup vs baseline: 5.4001x; 1.0149x over previous
#include <cuda_runtime.h>
#include <cuda_bf16.h>
#include <math.h>
#include <stdint.h>

#define BATCH 8
#define CH 128
#define NTOK 4096          // H*W
#define NGRP 32
#define CPG 4
#define EPSV 1e-5f
#define ATT_SCALE 0.08838834764831845f        // 1/sqrt(128)
#define QSC (ATT_SCALE * 1.4426950408889634f) // fold log2(e): exp -> ex2

// scratch (static device globals; no allocation allowed)
__device__ float g_normed[BATCH*CH*NTOK];            // NCHW
__device__ float g_q[BATCH*NTOK*CH];                 // token-major, CH-permuted
__device__ __nv_bfloat16 g_kb[BATCH*NTOK*CH];        // token-major, CH-permuted
__device__ __nv_bfloat16 g_vb[BATCH*CH*NTOK];        // channel-major, key-permuted
__device__ float g_attn[BATCH*NTOK*CH];
__device__ float g_mean[BATCH*NGRP];
__device__ float g_rstd[BATCH*NGRP];

// ---------------------------------------------------------------------------
// helpers
// ---------------------------------------------------------------------------
__device__ __forceinline__ unsigned f2tf(float f) {
    unsigned r;
    asm("cvt.rna.tf32.f32 %0, %1;" : "=r"(r) : "f"(f));
    return r;
}
__device__ __forceinline__ float ex2(float x) {
    float r;
    asm("ex2.approx.ftz.f32 %0, %1;" : "=f"(r) : "f"(x));
    return r;
}
// pack (lo, hi) floats into bf16x2 register (lo in low half)
__device__ __forceinline__ unsigned bfpack(float lo, float hi) {
    unsigned d;
    asm("cvt.rn.bf16x2.f32 %0, %1, %2;" : "=r"(d) : "f"(hi), "f"(lo));
    return d;
}
// tf32 m16n8k8 (qkv/proj)
__device__ __forceinline__ void mma8(float* d, const unsigned* a, unsigned b0, unsigned b1) {
    asm volatile(
        "mma.sync.aligned.m16n8k8.row.col.f32.tf32.tf32.f32 "
        "{%0,%1,%2,%3}, {%4,%5,%6,%7}, {%8,%9}, {%0,%1,%2,%3};"
        : "+f"(d[0]), "+f"(d[1]), "+f"(d[2]), "+f"(d[3])
        : "r"(a[0]), "r"(a[1]), "r"(a[2]), "r"(a[3]), "r"(b0), "r"(b1));
}
// bf16 m16n8k16 (flash)
__device__ __forceinline__ void mma16(float* d, const unsigned* a, unsigned b0, unsigned b1) {
    asm volatile(
        "mma.sync.aligned.m16n8k16.row.col.f32.bf16.bf16.f32 "
        "{%0,%1,%2,%3}, {%4,%5,%6,%7}, {%8,%9}, {%0,%1,%2,%3};"
        : "+f"(d[0]), "+f"(d[1]), "+f"(d[2]), "+f"(d[3])
        : "r"(a[0]), "r"(a[1]), "r"(a[2]), "r"(a[3]), "r"(b0), "r"(b1));
}

// ---------------------------------------------------------------------------
// K1: GroupNorm statistics
// ---------------------------------------------------------------------------
__global__ void gn_stats(const float* __restrict__ x) {
    const int bg = blockIdx.x;
    const float4* p = (const float4*)(x + (size_t)bg * CPG * NTOK);
    const int n4 = CPG * NTOK / 4;
    float s = 0.f, s2 = 0.f;
    for (int i = threadIdx.x; i < n4; i += blockDim.x) {
        float4 v = p[i];
        s  += v.x + v.y + v.z + v.w;
        s2 += v.x*v.x + v.y*v.y + v.z*v.z + v.w*v.w;
    }
    __shared__ float ss[256], ss2[256];
    ss[threadIdx.x] = s; ss2[threadIdx.x] = s2;
    __syncthreads();
    for (int st = 128; st > 0; st >>= 1) {
        if (threadIdx.x < st) {
            ss[threadIdx.x]  += ss[threadIdx.x + st];
            ss2[threadIdx.x] += ss2[threadIdx.x + st];
        }
        __syncthreads();
    }
    if (threadIdx.x == 0) {
        const float invn = 1.0f / (CPG * NTOK);
        float mu  = ss[0] * invn;
        float var = ss2[0] * invn - mu * mu;
        g_mean[bg] = mu;
        g_rstd[bg] = rsqrtf(var + EPSV);
    }
}

// ---------------------------------------------------------------------------
// K2: apply GroupNorm
// ---------------------------------------------------------------------------
__global__ void gn_apply(const float* __restrict__ x,
                         const float* __restrict__ gw,
                         const float* __restrict__ gb) {
    const int idx = blockIdx.x * blockDim.x + threadIdx.x;
    const int c_lin = idx >> 10;
    const int c = c_lin & (CH - 1);
    const int bg = c_lin >> 2;
    const float mu = g_mean[bg], rs = g_rstd[bg];
    const float a = rs * gw[c];
    const float bb = gb[c] - mu * a;
    float4 v = ((const float4*)x)[idx];
    v.x = v.x * a + bb;  v.y = v.y * a + bb;
    v.z = v.z * a + bb;  v.w = v.w * a + bb;
    ((float4*)g_normed)[idx] = v;
}

// ---------------------------------------------------------------------------
// K3: QKV projections via tf32 mma (unchanged from R10 — passing)
// ---------------------------------------------------------------------------
__global__ void __launch_bounds__(256) qkv_mma(
        const float* __restrict__ Wq, const float* __restrict__ bq,
        const float* __restrict__ Wk, const float* __restrict__ bk,
        const float* __restrict__ Wv, const float* __restrict__ bv) {
    extern __shared__ unsigned Ws[];
    const int tid = threadIdx.x;
    const int w = tid >> 5, l = tid & 31, g = l >> 2, t = l & 3;
    const int sel = blockIdx.y;
    const float* W    = (sel == 0) ? Wq : (sel == 1 ? Wk : Wv);
    const float* bias = (sel == 0) ? bq : (sel == 1 ? bk : bv);

    #pragma unroll
    for (int o = 0; o < 2; o++) {
        const int n = o * 64 + w * 8 + g;
        #pragma unroll
        for (int i = 0; i < 16; i++) {
            unsigned v0 = f2tf(W[n * CH + i * 8 + t]);
            unsigned v1 = f2tf(W[n * CH + i * 8 + t + 4]);
            const int qs = (4 * i + t) ^ ((n & 3) << 2);
            *(uint2*)&Ws[n * CH + 2 * qs] = make_uint2(v0, v1);
        }
    }
    __syncthreads();

    const int m0 = blockIdx.x * 128;
    const int bb = m0 >> 12;
    const int tok = (m0 & (NTOK - 1)) + w * 16 + g;
    const float* A = g_normed + (size_t)bb * CH * NTOK;

    unsigned aa[16][4];
    #pragma unroll
    for (int kt = 0; kt < 16; kt++) {
        aa[kt][0] = f2tf(A[(size_t)(kt*8 + t    ) * NTOK + tok    ]);
        aa[kt][1] = f2tf(A[(size_t)(kt*8 + t    ) * NTOK + tok + 8]);
        aa[kt][2] = f2tf(A[(size_t)(kt*8 + t + 4) * NTOK + tok    ]);
        aa[kt][3] = f2tf(A[(size_t)(kt*8 + t + 4) * NTOK + tok + 8]);
    }

    float acc[16][4];
    #pragma unroll
    for (int nt = 0; nt < 16; nt++)
        #pragma unroll
        for (int c = 0; c < 4; c++) acc[nt][c] = 0.f;

    const int sw = (g & 3) << 2;
    #pragma unroll
    for (int kt = 0; kt < 16; kt++) {
        const int qs = (kt * 4 + t) ^ sw;
        #pragma unroll
        for (int nt = 0; nt < 16; nt++) {
            uint2 b = *(uint2*)&Ws[(nt*8 + g) * CH + 2 * qs];
            mma8(acc[nt], aa[kt], b.x, b.y);
        }
    }

    const int gm = m0 + w * 16 + g;
    if (sel == 0) {
        // Q fp32, channel-permuted: logical ch nt*8+2t(+1) -> phys 16a+4t+2h(+1)
        #pragma unroll
        for (int nt = 0; nt < 16; nt++) {
            const int chl = nt * 8 + 2 * t;
            const float b0 = bias[chl], b1 = bias[chl + 1];
            const int phys = (nt >> 1) * 16 + 4 * t + (nt & 1) * 2;
            float2 v0 = {acc[nt][0] + b0, acc[nt][1] + b1};
            float2 v1 = {acc[nt][2] + b0, acc[nt][3] + b1};
            *(float2*)&g_q[(size_t)gm * CH + phys]       = v0;
            *(float2*)&g_q[(size_t)(gm + 8) * CH + phys] = v1;
        }
    } else if (sel == 1) {
        // K bf16, channel-permuted
        #pragma unroll
        for (int nt = 0; nt < 16; nt++) {
            const int chl = nt * 8 + 2 * t;
            const float b0 = bias[chl], b1 = bias[chl + 1];
            const int phys = (nt >> 1) * 16 + 4 * t + (nt & 1) * 2;
            __nv_bfloat162 v0, v1;
            v0.x = __float2bfloat16(acc[nt][0] + b0);
            v0.y = __float2bfloat16(acc[nt][1] + b1);
            v1.x = __float2bfloat16(acc[nt][2] + b0);
            v1.y = __float2bfloat16(acc[nt][3] + b1);
            *(__nv_bfloat162*)&g_kb[(size_t)gm * CH + phys]       = v0;
            *(__nv_bfloat162*)&g_kb[(size_t)(gm + 8) * CH + phys] = v1;
        }
    } else {
        // V bf16 channel-major, token-permuted within 16
        const int tloc = gm & (NTOK - 1);
        const int base16 = tloc - g;
        const int pg0 = 4 * (g >> 1) + (g & 1);
        #pragma unroll
        for (int nt = 0; nt < 16; nt++) {
            #pragma unroll
            for (int c = 0; c < 2; c++) {
                const int ch = nt * 8 + 2 * t + c;
                const float bo = bias[ch];
                const size_t a0 = ((size_t)bb * CH + ch) * NTOK + base16 + pg0;
                g_vb[a0]     = __float2bfloat16(acc[nt][c]     + bo);
                g_vb[a0 + 2] = __float2bfloat16(acc[nt][c + 2] + bo);
            }
        }
    }
}

// ---------------------------------------------------------------------------
// K4: bf16 m16n8k16 flash attention, v2 (occupancy 2).
//  Q: bf16-packed (QSC folded) in smem, row stride 288B (padding kills bank
//     conflicts: bank = (8g+8m+2t) mod 32, distinct per lds.64 phase).
//  K/V double-buffered as in R10.  __launch_bounds__(256,2) -> 2 CTAs/SM,
//  single wave (256 CTAs on 148 SMs).
// ---------------------------------------------------------------------------
#define KTILE_B 16384                          // 64*128*2
#define VTILE_B 16384                          // 128*64*2
#define QROW_B  288                            // 256B data + 32B pad
#define QS_BYTES (128 * QROW_B)                // 36864
#define FL_SMEM_BYTES (QS_BYTES + 2 * (KTILE_B + VTILE_B))   // 102400

__device__ __forceinline__ void stage_tile(const __nv_bfloat16* __restrict__ Kg,
                                           const __nv_bfloat16* __restrict__ Vt,
                                           uint32_t dK, uint32_t dV, int tid) {
    #pragma unroll
    for (int u = 0; u < 4; u++) {              // K: 64 rows x 16 chunks(16B)
        const int h = u * 256 + tid;
        const int row = h >> 4, c = h & 15;
        const int c2 = ((((c >> 1) + row) & 7) << 1) | (c & 1);
        asm volatile("cp.async.cg.shared.global [%0], [%1], 16;"
                     :: "r"(dK + row * 256 + c2 * 16), "l"(Kg + row * CH + c * 8));
    }
    #pragma unroll
    for (int u = 0; u < 4; u++) {              // V: 128 rows x 8 chunks(16B)
        const int h = u * 256 + tid;
        const int row = h >> 3, c = h & 7;
        const int c2 = ((((c >> 1) + row) & 3) << 1) | (c & 1);
        asm volatile("cp.async.cg.shared.global [%0], [%1], 16;"
                     :: "r"(dV + row * 128 + c2 * 16), "l"(Vt + (size_t)row * NTOK + c * 8));
    }
    asm volatile("cp.async.commit_group;");
}

__global__ void __launch_bounds__(256, 2) flash_mma() {
    extern __shared__ char smc[];
    const uint32_t smem_base = (uint32_t)__cvta_generic_to_shared(smc);
    const uint32_t kv_base = smem_base + QS_BYTES;

    const int blk = blockIdx.x;
    const int b = blk >> 5;
    const int qbase = (blk & 31) * 128;
    const int tid = threadIdx.x;
    const int w = tid >> 5, l = tid & 31, g = l >> 2, t = l & 3;
    const int r1 = w * 16 + g;

    // stage Q into smem: bf16-packed, QSC folded, phys channel order kept
    const float* Qg = g_q + (size_t)(b * NTOK + qbase) * CH;
    {
        const int row = tid >> 1, h = tid & 1;
        const float* src = &Qg[(size_t)row * CH + h * 64];
        uint4* dst = (uint4*)(smc + row * QROW_B + h * 128);
        #pragma unroll
        for (int i = 0; i < 8; i++) {
            float4 a  = *(const float4*)&src[i * 8];
            float4 b2 = *(const float4*)&src[i * 8 + 4];
            uint4 o;
            o.x = bfpack(a.x * QSC,  a.y * QSC);
            o.y = bfpack(a.z * QSC,  a.w * QSC);
            o.z = bfpack(b2.x * QSC, b2.y * QSC);
            o.w = bfpack(b2.z * QSC, b2.w * QSC);
            dst[i] = o;
        }
    }

    float oacc[16][4];
    #pragma unroll
    for (int nt = 0; nt < 16; nt++)
        #pragma unroll
        for (int c = 0; c < 4; c++) oacc[nt][c] = 0.f;
    float m1 = -1e30f, m2 = -1e30f, l1 = 0.f, l2 = 0.f;

    const __nv_bfloat16* KgB = g_kb + (size_t)b * NTOK * CH;   // [key][ch]
    const __nv_bfloat16* VgB = g_vb + (size_t)b * CH * NTOK;   // [ch][key]

    stage_tile(KgB, VgB, kv_base, kv_base + KTILE_B, tid);

    const char* qrow0 = smc + r1 * QROW_B + t * 8;
    const char* qrow1 = smc + (r1 + 8) * QROW_B + t * 8;

    #pragma unroll 1
    for (int jt = 0; jt < 64; jt++) {
        if (jt < 63) {
            const uint32_t nb = kv_base + ((jt + 1) & 1) * (KTILE_B + VTILE_B);
            stage_tile(KgB + (size_t)(jt + 1) * 64 * CH,
                       VgB + (size_t)(jt + 1) * 64,
                       nb, nb + KTILE_B, tid);
            asm volatile("cp.async.wait_group 1;");
        } else {
            asm volatile("cp.async.wait_group 0;");
        }
        __syncthreads();   // staging of jt visible to all; Q ready on jt==0

        const __nv_bfloat16* Kb =
            (const __nv_bfloat16*)(smc + QS_BYTES + (jt & 1) * (KTILE_B + VTILE_B));
        const __nv_bfloat16* Vb = Kb + KTILE_B / 2;

        // ---- S = (Q*qsc) @ K^T : Q frags from smem (transient regs) ----
        float sacc[8][4];
        #pragma unroll
        for (int nt = 0; nt < 8; nt++)
            #pragma unroll
            for (int c = 0; c < 4; c++) sacc[nt][c] = 0.f;

        #pragma unroll
        for (int m = 0; m < 8; m++) {
            const uint2 q0 = *(const uint2*)(qrow0 + m * 32);
            const uint2 q1 = *(const uint2*)(qrow1 + m * 32);
            const unsigned qa[4] = {q0.x, q1.x, q0.y, q1.y};
            const int moff = ((m + g) & 7) * 16 + 4 * t;
            #pragma unroll
            for (int nt = 0; nt < 8; nt++) {
                const uint2 kv = *(const uint2*)&Kb[(nt*8 + g) * 128 + moff];
                mma16(sacc[nt], qa, kv.x, kv.y);
            }
        }

        // ---- online softmax, exp2 domain (quad-local) ----
        float mx1 = -1e30f, mx2 = -1e30f;
        #pragma unroll
        for (int nt = 0; nt < 8; nt++) {
            mx1 = fmaxf(mx1, fmaxf(sacc[nt][0], sacc[nt][1]));
            mx2 = fmaxf(mx2, fmaxf(sacc[nt][2], sacc[nt][3]));
        }
        #pragma unroll
        for (int off = 1; off < 4; off <<= 1) {
            mx1 = fmaxf(mx1, __shfl_xor_sync(0xffffffffu, mx1, off));
            mx2 = fmaxf(mx2, __shfl_xor_sync(0xffffffffu, mx2, off));
        }
        const float mn1 = fmaxf(m1, mx1), mn2 = fmaxf(m2, mx2);
        const float al1 = ex2(m1 - mn1), al2 = ex2(m2 - mn2);
        float rs1 = 0.f, rs2 = 0.f;
        #pragma unroll
        for (int nt = 0; nt < 8; nt++) {
            sacc[nt][0] = ex2(sacc[nt][0] - mn1);
            sacc[nt][1] = ex2(sacc[nt][1] - mn1);
            sacc[nt][2] = ex2(sacc[nt][2] - mn2);
            sacc[nt][3] = ex2(sacc[nt][3] - mn2);
            rs1 += sacc[nt][0] + sacc[nt][1];
            rs2 += sacc[nt][2] + sacc[nt][3];
        }
        #pragma unroll
        for (int off = 1; off < 4; off <<= 1) {
            rs1 += __shfl_xor_sync(0xffffffffu, rs1, off);
            rs2 += __shfl_xor_sync(0xffffffffu, rs2, off);
        }
        l1 = l1 * al1 + rs1;  l2 = l2 * al2 + rs2;
        m1 = mn1;  m2 = mn2;
        const bool noresc = __all_sync(0xffffffffu, (al1 == 1.0f) && (al2 == 1.0f));
        if (!noresc) {
            #pragma unroll
            for (int nt = 0; nt < 16; nt++) {
                oacc[nt][0] *= al1;  oacc[nt][1] *= al1;
                oacc[nt][2] *= al2;  oacc[nt][3] *= al2;
            }
        }

        // ---- O += P @ V : P from sacc regs; V pairs via lds.64 ----
        #pragma unroll
        for (int kt = 0; kt < 4; kt++) {
            unsigned ar[4];
            ar[0] = bfpack(sacc[2*kt    ][0], sacc[2*kt    ][1]);
            ar[1] = bfpack(sacc[2*kt    ][2], sacc[2*kt    ][3]);
            ar[2] = bfpack(sacc[2*kt + 1][0], sacc[2*kt + 1][1]);
            ar[3] = bfpack(sacc[2*kt + 1][2], sacc[2*kt + 1][3]);
            const int koff = ((kt + g) & 3) * 16 + 4 * t;
            #pragma unroll
            for (int nt = 0; nt < 16; nt++) {
                const uint2 vv = *(const uint2*)&Vb[(nt*8 + g) * 64 + koff];
                mma16(oacc[nt], ar, vv.x, vv.y);
            }
        }
        __syncthreads();   // done reading buf[jt&1]
    }

    float* Og = g_attn + (size_t)(b * NTOK + qbase) * CH;
    const float inv1 = 1.0f / l1, inv2 = 1.0f / l2;
    #pragma unroll
    for (int nt = 0; nt < 16; nt++) {
        const int ch = nt * 8 + 2 * t;
        float2 v0 = {oacc[nt][0] * inv1, oacc[nt][1] * inv1};
        float2 v1 = {oacc[nt][2] * inv2, oacc[nt][3] * inv2};
        *(float2*)&Og[(size_t)r1 * CH + ch]       = v0;
        *(float2*)&Og[(size_t)(r1 + 8) * CH + ch] = v1;
    }
}

// ---------------------------------------------------------------------------
// K5: output projection via tf32 mma + bias + residual (unchanged)
// ---------------------------------------------------------------------------
__global__ void __launch_bounds__(256) proj_mma(const float* __restrict__ W,
                                                const float* __restrict__ bias,
                                                float* __restrict__ out) {
    extern __shared__ unsigned Ws[];
    const int tid = threadIdx.x;
    const int w = tid >> 5, l = tid & 31, g = l >> 2, t = l & 3;

    #pragma unroll
    for (int o = 0; o < 2; o++) {
        const int n = o * 64 + w * 8 + g;
        #pragma unroll
        for (int i = 0; i < 16; i++) {
            unsigned v0 = f2tf(W[n * CH + i*8 + t]);
            unsigned v1 = f2tf(W[n * CH + i*8 + t + 4]);
            const int qs = (4*i + t) ^ ((n & 3) << 2);
            *(uint2*)&Ws[n * CH + 2 * qs] = make_uint2(v0, v1);
        }
    }
    __syncthreads();

    const int m0 = blockIdx.x * 128;
    const int gm = m0 + w * 16 + g;
    unsigned aa[16][4];
    #pragma unroll
    for (int kt = 0; kt < 16; kt++) {
        aa[kt][0] = f2tf(g_attn[(size_t)gm       * CH + kt*8 + t    ]);
        aa[kt][1] = f2tf(g_attn[(size_t)(gm + 8) * CH + kt*8 + t    ]);
        aa[kt][2] = f2tf(g_attn[(size_t)gm       * CH + kt*8 + t + 4]);
        aa[kt][3] = f2tf(g_attn[(size_t)(gm + 8) * CH + kt*8 + t + 4]);
    }

    float acc[16][4];
    #pragma unroll
    for (int nt = 0; nt < 16; nt++)
        #pragma unroll
        for (int c = 0; c < 4; c++) acc[nt][c] = 0.f;

    const int sw = (g & 3) << 2;
    #pragma unroll
    for (int kt = 0; kt < 16; kt++) {
        const int qs = (kt * 4 + t) ^ sw;
        #pragma unroll
        for (int nt = 0; nt < 16; nt++) {
            uint2 b = *(uint2*)&Ws[(nt*8 + g) * CH + 2 * qs];
            mma8(acc[nt], aa[kt], b.x, b.y);
        }
    }

    const int bb = m0 >> 12;
    const int tok = (m0 & (NTOK - 1)) + w * 16 + g;
    #pragma unroll
    for (int nt = 0; nt < 16; nt++) {
        #pragma unroll
        for (int c = 0; c < 2; c++) {
            const int ch = nt * 8 + 2 * t + c;
            const float bo = bias[ch];
            const size_t a0 = ((size_t)bb * CH + ch) * NTOK + tok;
            out[a0]     = acc[nt][c]     + bo + g_normed[a0];
            out[a0 + 8] = acc[nt][c + 2] + bo + g_normed[a0 + 8];
        }
    }
}

// ---------------------------------------------------------------------------
extern "C" void kernel_launch(void* const* d_in, const int* in_sizes, int n_in,
                              void* d_out, int out_size) {
    const float* x   = (const float*)d_in[0];
    const float* gnw = (const float*)d_in[1];
    const float* gnb = (const float*)d_in[2];
    const float* Wq  = (const float*)d_in[3];
    const float* bq  = (const float*)d_in[4];
    const float* Wk  = (const float*)d_in[5];
    const float* bk  = (const float*)d_in[6];
    const float* Wv  = (const float*)d_in[7];
    const float* bv  = (const float*)d_in[8];
    const float* Wp  = (const float*)d_in[9];
    const float* bp  = (const float*)d_in[10];
    float* out = (float*)d_out;

    cudaFuncSetAttribute(flash_mma, cudaFuncAttributeMaxDynamicSharedMemorySize, FL_SMEM_BYTES);
    cudaFuncSetAttribute(qkv_mma,  cudaFuncAttributeMaxDynamicSharedMemorySize, 65536);
    cudaFuncSetAttribute(proj_mma, cudaFuncAttributeMaxDynamicSharedMemorySize, 65536);

    gn_stats<<<BATCH * NGRP, 256>>>(x);
    gn_apply<<<(BATCH * CH * NTOK / 4) / 256, 256>>>(x, gnw, gnb);
    qkv_mma<<<dim3(BATCH * NTOK / 128, 3), 256, 65536>>>(Wq, bq, Wk, bk, Wv, bv);
    flash_mma<<<BATCH * (NTOK / 128), 256, FL_SMEM_BYTES>>>();
    proj_mma<<<BATCH * NTOK / 128, 256, 65536>>>(Wp, bp, out);
}